// round 2
// baseline (speedup 1.0000x reference)
#include <cuda_runtime.h>
#include <cuda_bf16.h>
#include <cstdint>

// Problem constants (fixed by the reference)
#define N_ROUTES  16384
#define ROUTE_LEN 32
#define D_GRAPH   512
#define D_ROUTE   1024

// Ping-pong activation scratch (allocation-free: __device__ globals).
__device__ float g_act0[(size_t)N_ROUTES * D_ROUTE];
__device__ float g_act1[(size_t)N_ROUTES * D_ROUTE];

// Index-dtype detection flag: 1 => buffer is int32 layout, 0 => int64 layout.
__device__ int g_idx_is_i32;

// ---------------------------------------------------------------------------
// Index dtype detection.
// Scan the first N_ROUTES*ROUTE_LEN int32 words (safe for both layouts).
// int64 layout: odd words are high words of values in [0, 100000) -> all 0.
// int32 layout: odd words are random indices -> nonzero w.p. ~1.
// ---------------------------------------------------------------------------
__global__ void detect_init_kernel() { g_idx_is_i32 = 0; }

__global__ __launch_bounds__(256) void detect_idx_kernel(const unsigned int* __restrict__ w)
{
    const int n_words = N_ROUTES * ROUTE_LEN;   // 524288
    int found = 0;
    for (int j = (blockIdx.x * blockDim.x + threadIdx.x) * 2 + 1;
         j < n_words;
         j += gridDim.x * blockDim.x * 2) {
        if (w[j] != 0u) { found = 1; break; }
    }
    if (found) atomicOr(&g_idx_is_i32, 1);
}

// ---------------------------------------------------------------------------
// Kernel 1: gather rows + max over 32 route positions.
// One block per route. 128 threads, each owns one float4 column group.
// ---------------------------------------------------------------------------
__global__ __launch_bounds__(128) void gather_max_kernel(
    const float* __restrict__ ge,            // [N_NODES, 512]
    const int* __restrict__ idx32,           // [N_ROUTES, 32] if int32
    const long long* __restrict__ idx64,     // same buffer if int64
    float* __restrict__ out)                 // [N_ROUTES, 512]
{
    const int r = blockIdx.x;
    __shared__ int s_idx[ROUTE_LEN];
    if (threadIdx.x < ROUTE_LEN) {
        int v;
        if (g_idx_is_i32) v = idx32[(size_t)r * ROUTE_LEN + threadIdx.x];
        else              v = (int)idx64[(size_t)r * ROUTE_LEN + threadIdx.x];
        s_idx[threadIdx.x] = v;
    }
    __syncthreads();

    const int c = threadIdx.x;  // float4 column index, 0..127
    float4 m = make_float4(-3.4e38f, -3.4e38f, -3.4e38f, -3.4e38f);

    #pragma unroll 8
    for (int l = 0; l < ROUTE_LEN; l++) {
        const float4* row = (const float4*)(ge + (size_t)s_idx[l] * D_GRAPH);
        float4 v = __ldg(row + c);
        m.x = fmaxf(m.x, v.x);
        m.y = fmaxf(m.y, v.y);
        m.z = fmaxf(m.z, v.z);
        m.w = fmaxf(m.w, v.w);
    }
    ((float4*)(out + (size_t)r * D_GRAPH))[c] = m;
}

// ---------------------------------------------------------------------------
// Kernel 2: fp32 SGEMM + bias + ReLU.
// C[M,N] = relu(A[M,K] @ B[K,N] + bias[N])
// 128x128 block tile, BK=8, 8x8 per-thread tile, 256 threads.
// ---------------------------------------------------------------------------
#define BM 128
#define BN 128
#define BKK 8
#define TM 8
#define TN 8

__global__ __launch_bounds__(256) void sgemm_bias_relu(
    int M, int N, int K,
    const float* __restrict__ A,
    const float* __restrict__ B,
    const float* __restrict__ bias,
    float* __restrict__ C)
{
    __shared__ float As[BKK][BM];   // A tile, transposed for contiguous M reads
    __shared__ float Bs[BKK][BN];

    const int tid = threadIdx.x;
    const int tx = tid & 15;        // 0..15 -> N direction
    const int ty = tid >> 4;        // 0..15 -> M direction
    const int rowBase = blockIdx.y * BM;
    const int colBase = blockIdx.x * BN;

    // A-tile load mapping: 128 rows x 8 k -> each thread one float4 along K
    const int aRow = tid >> 1;          // 0..127
    const int aCol = (tid & 1) * 4;     // 0 or 4
    // B-tile load mapping: 8 k-rows x 128 cols -> each thread one float4 along N
    const int bRow = tid >> 5;          // 0..7
    const int bCol = (tid & 31) * 4;    // 0..124

    const float* Aptr = A + (size_t)(rowBase + aRow) * K + aCol;
    const float* Bptr = B + (size_t)bRow * N + colBase + bCol;

    float acc[TM][TN];
    #pragma unroll
    for (int i = 0; i < TM; i++)
        #pragma unroll
        for (int j = 0; j < TN; j++) acc[i][j] = 0.0f;

    for (int k0 = 0; k0 < K; k0 += BKK) {
        float4 av = *(const float4*)(Aptr + k0);
        As[aCol + 0][aRow] = av.x;
        As[aCol + 1][aRow] = av.y;
        As[aCol + 2][aRow] = av.z;
        As[aCol + 3][aRow] = av.w;
        *(float4*)(&Bs[bRow][bCol]) = *(const float4*)(Bptr + (size_t)k0 * N);
        __syncthreads();

        #pragma unroll
        for (int k = 0; k < BKK; k++) {
            float ar[TM], br[TN];
            float4 a0 = *(const float4*)(&As[k][ty * TM]);
            float4 a1 = *(const float4*)(&As[k][ty * TM + 4]);
            ar[0] = a0.x; ar[1] = a0.y; ar[2] = a0.z; ar[3] = a0.w;
            ar[4] = a1.x; ar[5] = a1.y; ar[6] = a1.z; ar[7] = a1.w;
            float4 b0 = *(const float4*)(&Bs[k][tx * TN]);
            float4 b1 = *(const float4*)(&Bs[k][tx * TN + 4]);
            br[0] = b0.x; br[1] = b0.y; br[2] = b0.z; br[3] = b0.w;
            br[4] = b1.x; br[5] = b1.y; br[6] = b1.z; br[7] = b1.w;

            #pragma unroll
            for (int i = 0; i < TM; i++)
                #pragma unroll
                for (int j = 0; j < TN; j++)
                    acc[i][j] = fmaf(ar[i], br[j], acc[i][j]);
        }
        __syncthreads();
    }

    // Epilogue: bias + ReLU, float4 stores
    #pragma unroll
    for (int i = 0; i < TM; i++) {
        const int row = rowBase + ty * TM + i;
        float* crow = C + (size_t)row * N;
        #pragma unroll
        for (int j = 0; j < TN; j += 4) {
            const int col = colBase + tx * TN + j;
            float4 v;
            v.x = fmaxf(acc[i][j + 0] + __ldg(bias + col + 0), 0.0f);
            v.y = fmaxf(acc[i][j + 1] + __ldg(bias + col + 1), 0.0f);
            v.z = fmaxf(acc[i][j + 2] + __ldg(bias + col + 2), 0.0f);
            v.w = fmaxf(acc[i][j + 3] + __ldg(bias + col + 3), 0.0f);
            *(float4*)(crow + col) = v;
        }
    }
}

// ---------------------------------------------------------------------------
// kernel_launch: detect idx dtype, gather/max, then three GEMM+bias+ReLU.
// Inputs (metadata order): graph_embedding, locations_idx, W0, b0, W1, b1, W2, b2
// ---------------------------------------------------------------------------
extern "C" void kernel_launch(void* const* d_in, const int* in_sizes, int n_in,
                              void* d_out, int out_size)
{
    const float* ge  = (const float*)d_in[0];
    const void*  idx = d_in[1];
    const float* W0  = (const float*)d_in[2];
    const float* b0  = (const float*)d_in[3];
    const float* W1  = (const float*)d_in[4];
    const float* b1  = (const float*)d_in[5];
    const float* W2  = (const float*)d_in[6];
    const float* b2  = (const float*)d_in[7];
    float* out = (float*)d_out;

    float* act0;
    float* act1;
    cudaGetSymbolAddress((void**)&act0, g_act0);
    cudaGetSymbolAddress((void**)&act1, g_act1);

    // 0. Detect index dtype (int32 vs int64) inside the graph.
    detect_init_kernel<<<1, 1>>>();
    detect_idx_kernel<<<256, 256>>>((const unsigned int*)idx);

    // 1. routes_emb = max over route positions of gathered rows -> act0 [16384,512]
    gather_max_kernel<<<N_ROUTES, 128>>>(ge, (const int*)idx, (const long long*)idx, act0);

    // 2. act1 = relu(act0 @ W0 + b0)   [16384,512] x [512,1024]
    dim3 grid(D_ROUTE / BN, N_ROUTES / BM);
    sgemm_bias_relu<<<grid, 256>>>(N_ROUTES, D_ROUTE, D_GRAPH, act0, W0, b0, act1);

    // 3. act0 = relu(act1 @ W1 + b1)   [16384,1024] x [1024,1024]
    sgemm_bias_relu<<<grid, 256>>>(N_ROUTES, D_ROUTE, D_ROUTE, act1, W1, b1, act0);

    // 4. out = relu(act0 @ W2 + b2)    [16384,1024] x [1024,1024]
    sgemm_bias_relu<<<grid, 256>>>(N_ROUTES, D_ROUTE, D_ROUTE, act0, W2, b2, out);
}

// round 4
// speedup vs baseline: 3.2151x; 3.2151x over previous
#include <cuda_runtime.h>
#include <cuda_bf16.h>
#include <cstdint>

// Problem constants
#define N_ROUTES  16384
#define ROUTE_LEN 32
#define D_GRAPH   512
#define D_ROUTE   1024

using bf16 = __nv_bfloat16;

// ---------------------------------------------------------------------------
// Device scratch (allocation-free). Activations ping-pong as bf16 hi/lo splits.
// ---------------------------------------------------------------------------
__device__ __align__(256) bf16 g_ahi[(size_t)N_ROUTES * D_ROUTE];
__device__ __align__(256) bf16 g_alo[(size_t)N_ROUTES * D_ROUTE];
__device__ __align__(256) bf16 g_bhi[(size_t)N_ROUTES * D_ROUTE];
__device__ __align__(256) bf16 g_blo[(size_t)N_ROUTES * D_ROUTE];
// Transposed bf16 weights [N,K]
#define W0_OFF 0
#define W1_OFF (1024*512)
#define W2_OFF (1024*512 + 1024*1024)
#define W_ELEMS (1024*512 + 1024*1024 + 1024*1024)
__device__ __align__(256) bf16 g_whi[W_ELEMS];
__device__ __align__(256) bf16 g_wlo[W_ELEMS];
__device__ int g_idx_is_i32;

// ---------------------------------------------------------------------------
// Helpers
// ---------------------------------------------------------------------------
__device__ __forceinline__ uint32_t swz128(uint32_t b) { return b ^ ((b >> 3) & 0x70); }

__device__ __forceinline__ uint32_t smem_u32(const void* p) {
    uint32_t a;
    asm("{ .reg .u64 t; cvta.to.shared.u64 t, %1; cvt.u32.u64 %0, t; }" : "=r"(a) : "l"(p));
    return a;
}

__device__ __forceinline__ void cp16(uint32_t dst, const void* src) {
    asm volatile("cp.async.cg.shared.global [%0], [%1], 16;" :: "r"(dst), "l"(src) : "memory");
}
__device__ __forceinline__ void cp_commit() { asm volatile("cp.async.commit_group;" ::: "memory"); }
__device__ __forceinline__ void cp_wait1() { asm volatile("cp.async.wait_group 1;" ::: "memory"); }

__device__ __forceinline__ void ldsm_x4(uint32_t* r, uint32_t addr) {
    asm volatile("ldmatrix.sync.aligned.m8n8.x4.shared.b16 {%0,%1,%2,%3}, [%4];"
                 : "=r"(r[0]), "=r"(r[1]), "=r"(r[2]), "=r"(r[3]) : "r"(addr));
}
__device__ __forceinline__ void ldsm_x2(uint32_t* r, uint32_t addr) {
    asm volatile("ldmatrix.sync.aligned.m8n8.x2.shared.b16 {%0,%1}, [%2];"
                 : "=r"(r[0]), "=r"(r[1]) : "r"(addr));
}

__device__ __forceinline__ void mma16816(float* d, const uint32_t* a, const uint32_t* b) {
    asm volatile(
        "mma.sync.aligned.m16n8k16.row.col.f32.bf16.bf16.f32 "
        "{%0,%1,%2,%3}, {%4,%5,%6,%7}, {%8,%9}, {%0,%1,%2,%3};"
        : "+f"(d[0]), "+f"(d[1]), "+f"(d[2]), "+f"(d[3])
        : "r"(a[0]), "r"(a[1]), "r"(a[2]), "r"(a[3]), "r"(b[0]), "r"(b[1]));
}

// ---------------------------------------------------------------------------
// Index dtype detection (int32 vs int64 layout).
// ---------------------------------------------------------------------------
__global__ void detect_init_kernel() { g_idx_is_i32 = 0; }

__global__ __launch_bounds__(256) void detect_idx_kernel(const unsigned int* __restrict__ w) {
    const int n_words = N_ROUTES * ROUTE_LEN;
    int found = 0;
    for (int j = (blockIdx.x * blockDim.x + threadIdx.x) * 2 + 1;
         j < n_words; j += gridDim.x * blockDim.x * 2) {
        if (w[j] != 0u) { found = 1; break; }
    }
    if (found) atomicOr(&g_idx_is_i32, 1);
}

// ---------------------------------------------------------------------------
// Gather + max -> bf16 hi/lo. 256 threads/route: 2 halves of 16 positions each,
// combined through SMEM. Doubles memory-level parallelism vs 128-thread version.
// ---------------------------------------------------------------------------
__global__ __launch_bounds__(256) void gather_max_kernel(
    const float* __restrict__ ge,
    const int* __restrict__ idx32,
    const long long* __restrict__ idx64,
    bf16* __restrict__ out_hi, bf16* __restrict__ out_lo)
{
    const int r = blockIdx.x;
    __shared__ int s_idx[ROUTE_LEN];
    __shared__ float4 s_red[128];

    if (threadIdx.x < ROUTE_LEN) {
        int v;
        if (g_idx_is_i32) v = idx32[(size_t)r * ROUTE_LEN + threadIdx.x];
        else              v = (int)idx64[(size_t)r * ROUTE_LEN + threadIdx.x];
        s_idx[threadIdx.x] = v;
    }
    __syncthreads();

    const int c    = threadIdx.x & 127;   // float4 column group
    const int half = threadIdx.x >> 7;    // 0 or 1
    float4 m = make_float4(-3.4e38f, -3.4e38f, -3.4e38f, -3.4e38f);

    #pragma unroll 16
    for (int l = half * 16; l < half * 16 + 16; l++) {
        const float4* row = (const float4*)(ge + (size_t)s_idx[l] * D_GRAPH);
        float4 v = __ldg(row + c);
        m.x = fmaxf(m.x, v.x); m.y = fmaxf(m.y, v.y);
        m.z = fmaxf(m.z, v.z); m.w = fmaxf(m.w, v.w);
    }

    if (half == 1) s_red[c] = m;
    __syncthreads();
    if (half == 0) {
        float4 o = s_red[c];
        m.x = fmaxf(m.x, o.x); m.y = fmaxf(m.y, o.y);
        m.z = fmaxf(m.z, o.z); m.w = fmaxf(m.w, o.w);

        float vv[4] = {m.x, m.y, m.z, m.w};
        bf16 h[4], lo[4];
        #pragma unroll
        for (int j = 0; j < 4; j++) {
            h[j]  = __float2bfloat16(vv[j]);
            lo[j] = __float2bfloat16(vv[j] - __bfloat162float(h[j]));
        }
        const size_t off = (size_t)r * D_GRAPH + c * 4;
        __nv_bfloat162 h01 = __halves2bfloat162(h[0], h[1]);
        __nv_bfloat162 h23 = __halves2bfloat162(h[2], h[3]);
        __nv_bfloat162 l01 = __halves2bfloat162(lo[0], lo[1]);
        __nv_bfloat162 l23 = __halves2bfloat162(lo[2], lo[3]);
        *(uint2*)(out_hi + off) = make_uint2(*(uint32_t*)&h01, *(uint32_t*)&h23);
        *(uint2*)(out_lo + off) = make_uint2(*(uint32_t*)&l01, *(uint32_t*)&l23);
    }
}

// ---------------------------------------------------------------------------
// Weight prep: W[K,N] fp32 -> transposed bf16 hi/lo [N,K]
// ---------------------------------------------------------------------------
__global__ __launch_bounds__(256) void wsplit_kernel(
    const float* __restrict__ W, int K, int N,
    bf16* __restrict__ Whi, bf16* __restrict__ Wlo)
{
    __shared__ float t[32][33];
    const int n0 = blockIdx.x * 32;
    const int k0 = blockIdx.y * 32;
    const int tx = threadIdx.x, ty = threadIdx.y;

    #pragma unroll
    for (int i = 0; i < 4; i++)
        t[ty + i * 8][tx] = W[(size_t)(k0 + ty + i * 8) * N + n0 + tx];
    __syncthreads();

    #pragma unroll
    for (int i = 0; i < 4; i++) {
        const int n = n0 + ty + i * 8;
        const int k = k0 + tx;
        float v = t[tx][ty + i * 8];
        bf16 h = __float2bfloat16(v);
        bf16 l = __float2bfloat16(v - __bfloat162float(h));
        Whi[(size_t)n * K + k] = h;
        Wlo[(size_t)n * K + k] = l;
    }
}

// ---------------------------------------------------------------------------
// bf16x3 GEMM on mma.sync: C[M,128-block of 1024] = relu(A @ B^T + bias)
// A: hi/lo bf16 [M,K] row-major. B: hi/lo bf16 [1024,K] K-major.
// 128x128 CTA tile, 8 warps (2 M x 4 N), warp tile 64x32, m16n8k16 fragments.
// 2-stage cp.async pipeline, K-chunk = 64 bf16 (128B rows, SW128 swizzle).
// ---------------------------------------------------------------------------
#define STAGE_BYTES 65536
#define T_AHI 0
#define T_ALO 16384
#define T_BHI 32768
#define T_BLO 49152

__device__ __forceinline__ void load_chunk(
    uint32_t sbase, int c, int tid, int m0, int n0, int K,
    const bf16* Ahi, const bf16* Alo, const bf16* Bhi, const bf16* Blo)
{
    const int r0  = tid >> 3;      // 0..31
    const int seg = tid & 7;       // 0..7 (16B segments of a 128B row)
    const uint32_t st = sbase + (uint32_t)(c & 1) * STAGE_BYTES;
    const size_t koff = (size_t)c * 64 + seg * 8;   // bf16 elements
    #pragma unroll
    for (int i = 0; i < 4; i++) {
        const int row = r0 + i * 32;
        const uint32_t sw = swz128((uint32_t)(row * 128 + seg * 16));
        cp16(st + T_AHI + sw, Ahi + (size_t)(m0 + row) * K + koff);
        cp16(st + T_ALO + sw, Alo + (size_t)(m0 + row) * K + koff);
        cp16(st + T_BHI + sw, Bhi + (size_t)(n0 + row) * K + koff);
        cp16(st + T_BLO + sw, Blo + (size_t)(n0 + row) * K + koff);
    }
    cp_commit();
}

__global__ __launch_bounds__(256) void gemm_bf16x3(
    int K, int nchunks,
    const bf16* __restrict__ Ahi, const bf16* __restrict__ Alo,
    const bf16* __restrict__ Bhi, const bf16* __restrict__ Blo,
    const float* __restrict__ bias,
    float* __restrict__ Cf, bf16* __restrict__ Chi, bf16* __restrict__ Clo)
{
    extern __shared__ __align__(1024) char smem[];
    __shared__ float s_bias[128];

    const int tid  = threadIdx.x;
    const int wid  = tid >> 5;
    const int lane = tid & 31;
    const int m0 = blockIdx.y * 128;
    const int n0 = blockIdx.x * 128;
    const int wm = (wid >> 2) * 64;   // warp M offset within tile (0/64)
    const int wn = (wid & 3) * 32;    // warp N offset within tile (0/32/64/96)

    const uint32_t sbase = smem_u32(smem);
    if (tid < 128) s_bias[tid] = bias[n0 + tid];

    // Preload 2 stages
    load_chunk(sbase, 0, tid, m0, n0, K, Ahi, Alo, Bhi, Blo);
    if (nchunks > 1) load_chunk(sbase, 1, tid, m0, n0, K, Ahi, Alo, Bhi, Blo);

    float acc[4][4][4];
    #pragma unroll
    for (int i = 0; i < 4; i++)
        #pragma unroll
        for (int j = 0; j < 4; j++)
            #pragma unroll
            for (int q = 0; q < 4; q++) acc[i][j][q] = 0.0f;

    for (int c = 0; c < nchunks; c++) {
        cp_wait1();
        __syncthreads();

        const uint32_t st = sbase + (uint32_t)(c & 1) * STAGE_BYTES;

        #pragma unroll
        for (int ks = 0; ks < 4; ks++) {
            const uint32_t kb = ks * 32;   // byte offset of this k16 within 128B row

            // B fragments for the 4 n-tiles (hi & lo)
            uint32_t bh[4][2], bl[4][2];
            #pragma unroll
            for (int nt = 0; nt < 4; nt++) {
                const uint32_t off = swz128(
                    (uint32_t)((wn + nt * 8 + (lane & 7)) * 128) + kb + ((lane >> 3) & 1) * 16);
                ldsm_x2(bh[nt], st + T_BHI + off);
                ldsm_x2(bl[nt], st + T_BLO + off);
            }

            #pragma unroll
            for (int mt = 0; mt < 4; mt++) {
                const uint32_t aoff = swz128(
                    (uint32_t)((wm + mt * 16 + (lane & 15)) * 128) + kb + ((lane >> 4) & 1) * 16);
                uint32_t ah[4], al[4];
                ldsm_x4(ah, st + T_AHI + aoff);
                ldsm_x4(al, st + T_ALO + aoff);
                #pragma unroll
                for (int nt = 0; nt < 4; nt++) {
                    mma16816(acc[mt][nt], ah, bh[nt]);
                    mma16816(acc[mt][nt], ah, bl[nt]);
                    mma16816(acc[mt][nt], al, bh[nt]);
                }
            }
        }

        __syncthreads();
        if (c + 2 < nchunks)
            load_chunk(sbase, c + 2, tid, m0, n0, K, Ahi, Alo, Bhi, Blo);
    }

    // Epilogue: fragment (mt,nt), lane l holds rows {l/4, l/4+8}, cols {2(l%4), +1}
    const int rbase = m0 + wm + (lane >> 2);
    const int cloc0 = wn + (lane & 3) * 2;
    #pragma unroll
    for (int mt = 0; mt < 4; mt++) {
        #pragma unroll
        for (int half = 0; half < 2; half++) {
            const int row = rbase + mt * 16 + half * 8;
            #pragma unroll
            for (int nt = 0; nt < 4; nt++) {
                const int cl = cloc0 + nt * 8;
                float v0 = fmaxf(acc[mt][nt][half * 2 + 0] + s_bias[cl + 0], 0.0f);
                float v1 = fmaxf(acc[mt][nt][half * 2 + 1] + s_bias[cl + 1], 0.0f);
                const size_t off = (size_t)row * D_ROUTE + n0 + cl;
                if (Cf) {
                    *(float2*)(Cf + off) = make_float2(v0, v1);
                } else {
                    bf16 h0 = __float2bfloat16(v0);
                    bf16 h1 = __float2bfloat16(v1);
                    bf16 l0 = __float2bfloat16(v0 - __bfloat162float(h0));
                    bf16 l1 = __float2bfloat16(v1 - __bfloat162float(h1));
                    __nv_bfloat162 hp = __halves2bfloat162(h0, h1);
                    __nv_bfloat162 lp = __halves2bfloat162(l0, l1);
                    *(uint32_t*)(Chi + off) = *(uint32_t*)&hp;
                    *(uint32_t*)(Clo + off) = *(uint32_t*)&lp;
                }
            }
        }
    }
}

// ---------------------------------------------------------------------------
// kernel_launch
// Inputs: graph_embedding, locations_idx, W0, b0, W1, b1, W2, b2
// ---------------------------------------------------------------------------
extern "C" void kernel_launch(void* const* d_in, const int* in_sizes, int n_in,
                              void* d_out, int out_size)
{
    const float* ge  = (const float*)d_in[0];
    const void*  idx = d_in[1];
    const float* W0  = (const float*)d_in[2];
    const float* b0  = (const float*)d_in[3];
    const float* W1  = (const float*)d_in[4];
    const float* b1  = (const float*)d_in[5];
    const float* W2  = (const float*)d_in[6];
    const float* b2  = (const float*)d_in[7];
    float* out = (float*)d_out;

    bf16 *ahi, *alo, *bhi, *blo, *whi, *wlo;
    cudaGetSymbolAddress((void**)&ahi, g_ahi);
    cudaGetSymbolAddress((void**)&alo, g_alo);
    cudaGetSymbolAddress((void**)&bhi, g_bhi);
    cudaGetSymbolAddress((void**)&blo, g_blo);
    cudaGetSymbolAddress((void**)&whi, g_whi);
    cudaGetSymbolAddress((void**)&wlo, g_wlo);

    const int smem_bytes = 2 * STAGE_BYTES;   // 128 KB
    cudaFuncSetAttribute(gemm_bf16x3, cudaFuncAttributeMaxDynamicSharedMemorySize, smem_bytes);

    // 0. index dtype detection
    detect_init_kernel<<<1, 1>>>();
    detect_idx_kernel<<<256, 256>>>((const unsigned int*)idx);

    // 1. weight prep (transpose + bf16 split)
    {
        dim3 blk(32, 8);
        wsplit_kernel<<<dim3(1024 / 32, 512 / 32),  blk>>>(W0, 512,  1024, whi + W0_OFF, wlo + W0_OFF);
        wsplit_kernel<<<dim3(1024 / 32, 1024 / 32), blk>>>(W1, 1024, 1024, whi + W1_OFF, wlo + W1_OFF);
        wsplit_kernel<<<dim3(1024 / 32, 1024 / 32), blk>>>(W2, 1024, 1024, whi + W2_OFF, wlo + W2_OFF);
    }

    // 2. gather + max -> bf16 hi/lo activations (stride 512)
    gather_max_kernel<<<N_ROUTES, 256>>>(ge, (const int*)idx, (const long long*)idx, ahi, alo);

    // 3. three GEMM layers on the tensor pipe
    dim3 grid(D_ROUTE / 128, N_ROUTES / 128);   // (8, 128)
    gemm_bf16x3<<<grid, 256, smem_bytes>>>(512, 8,  ahi, alo, whi + W0_OFF, wlo + W0_OFF, b0,
                                           nullptr, bhi, blo);
    gemm_bf16x3<<<grid, 256, smem_bytes>>>(1024, 16, bhi, blo, whi + W1_OFF, wlo + W1_OFF, b1,
                                           nullptr, ahi, alo);
    gemm_bf16x3<<<grid, 256, smem_bytes>>>(1024, 16, ahi, alo, whi + W2_OFF, wlo + W2_OFF, b2,
                                           out, nullptr, nullptr);
}

// round 5
// speedup vs baseline: 3.9876x; 1.2403x over previous
#include <cuda_runtime.h>
#include <cuda_fp16.h>
#include <cstdint>

// Problem constants
#define N_ROUTES  16384
#define ROUTE_LEN 32
#define D_GRAPH   512
#define D_ROUTE   1024

// ---------------------------------------------------------------------------
// Device scratch (allocation-free).
// Activations ping-pong as fp16 hi/lo splits; weights are single fp16 [N,K].
// ---------------------------------------------------------------------------
__device__ __align__(256) __half g_ahi[(size_t)N_ROUTES * D_ROUTE];
__device__ __align__(256) __half g_alo[(size_t)N_ROUTES * D_ROUTE];
__device__ __align__(256) __half g_bhi[(size_t)N_ROUTES * D_ROUTE];
__device__ __align__(256) __half g_blo[(size_t)N_ROUTES * D_ROUTE];
#define W0_OFF 0
#define W1_OFF (1024*512)
#define W2_OFF (1024*512 + 1024*1024)
#define W_ELEMS (1024*512 + 1024*1024 + 1024*1024)
__device__ __align__(256) __half g_w[W_ELEMS];
__device__ int g_idx_is_i32;

// ---------------------------------------------------------------------------
// Helpers
// ---------------------------------------------------------------------------
__device__ __forceinline__ uint32_t swz128(uint32_t b) { return b ^ ((b >> 3) & 0x70); }

__device__ __forceinline__ uint32_t smem_u32(const void* p) {
    uint32_t a;
    asm("{ .reg .u64 t; cvta.to.shared.u64 t, %1; cvt.u32.u64 %0, t; }" : "=r"(a) : "l"(p));
    return a;
}

__device__ __forceinline__ void cp16(uint32_t dst, const void* src) {
    asm volatile("cp.async.cg.shared.global [%0], [%1], 16;" :: "r"(dst), "l"(src) : "memory");
}
__device__ __forceinline__ void cp_commit() { asm volatile("cp.async.commit_group;" ::: "memory"); }
__device__ __forceinline__ void cp_wait2() { asm volatile("cp.async.wait_group 2;" ::: "memory"); }

__device__ __forceinline__ void ldsm_x4(uint32_t* r, uint32_t addr) {
    asm volatile("ldmatrix.sync.aligned.m8n8.x4.shared.b16 {%0,%1,%2,%3}, [%4];"
                 : "=r"(r[0]), "=r"(r[1]), "=r"(r[2]), "=r"(r[3]) : "r"(addr));
}
__device__ __forceinline__ void ldsm_x2(uint32_t* r, uint32_t addr) {
    asm volatile("ldmatrix.sync.aligned.m8n8.x2.shared.b16 {%0,%1}, [%2];"
                 : "=r"(r[0]), "=r"(r[1]) : "r"(addr));
}

__device__ __forceinline__ void mma16816(float* d, const uint32_t* a, const uint32_t* b) {
    asm volatile(
        "mma.sync.aligned.m16n8k16.row.col.f32.f16.f16.f32 "
        "{%0,%1,%2,%3}, {%4,%5,%6,%7}, {%8,%9}, {%0,%1,%2,%3};"
        : "+f"(d[0]), "+f"(d[1]), "+f"(d[2]), "+f"(d[3])
        : "r"(a[0]), "r"(a[1]), "r"(a[2]), "r"(a[3]), "r"(b[0]), "r"(b[1]));
}

// ---------------------------------------------------------------------------
// Index dtype detection (int32 vs int64 layout).
// ---------------------------------------------------------------------------
__global__ void detect_init_kernel() { g_idx_is_i32 = 0; }

__global__ __launch_bounds__(256) void detect_idx_kernel(const unsigned int* __restrict__ w) {
    const int n_words = N_ROUTES * ROUTE_LEN;
    int found = 0;
    for (int j = (blockIdx.x * blockDim.x + threadIdx.x) * 2 + 1;
         j < n_words; j += gridDim.x * blockDim.x * 2) {
        if (w[j] != 0u) { found = 1; break; }
    }
    if (found) atomicOr(&g_idx_is_i32, 1);
}

// ---------------------------------------------------------------------------
// Gather + max -> fp16 hi/lo. 256 threads/route: 2 halves of 16 positions,
// combined through SMEM.
// ---------------------------------------------------------------------------
__global__ __launch_bounds__(256) void gather_max_kernel(
    const float* __restrict__ ge,
    const int* __restrict__ idx32,
    const long long* __restrict__ idx64,
    __half* __restrict__ out_hi, __half* __restrict__ out_lo)
{
    const int r = blockIdx.x;
    __shared__ int s_idx[ROUTE_LEN];
    __shared__ float4 s_red[128];

    if (threadIdx.x < ROUTE_LEN) {
        int v;
        if (g_idx_is_i32) v = idx32[(size_t)r * ROUTE_LEN + threadIdx.x];
        else              v = (int)idx64[(size_t)r * ROUTE_LEN + threadIdx.x];
        s_idx[threadIdx.x] = v;
    }
    __syncthreads();

    const int c    = threadIdx.x & 127;
    const int half = threadIdx.x >> 7;
    float4 m = make_float4(-3.4e38f, -3.4e38f, -3.4e38f, -3.4e38f);

    #pragma unroll 16
    for (int l = half * 16; l < half * 16 + 16; l++) {
        const float4* row = (const float4*)(ge + (size_t)s_idx[l] * D_GRAPH);
        float4 v = __ldg(row + c);
        m.x = fmaxf(m.x, v.x); m.y = fmaxf(m.y, v.y);
        m.z = fmaxf(m.z, v.z); m.w = fmaxf(m.w, v.w);
    }

    if (half == 1) s_red[c] = m;
    __syncthreads();
    if (half == 0) {
        float4 o = s_red[c];
        m.x = fmaxf(m.x, o.x); m.y = fmaxf(m.y, o.y);
        m.z = fmaxf(m.z, o.z); m.w = fmaxf(m.w, o.w);

        float vv[4] = {m.x, m.y, m.z, m.w};
        __half h[4], lo[4];
        #pragma unroll
        for (int j = 0; j < 4; j++) {
            h[j]  = __float2half_rn(vv[j]);
            lo[j] = __float2half_rn(vv[j] - __half2float(h[j]));
        }
        const size_t off = (size_t)r * D_GRAPH + c * 4;
        __half2 h01 = __halves2half2(h[0], h[1]);
        __half2 h23 = __halves2half2(h[2], h[3]);
        __half2 l01 = __halves2half2(lo[0], lo[1]);
        __half2 l23 = __halves2half2(lo[2], lo[3]);
        *(uint2*)(out_hi + off) = make_uint2(*(uint32_t*)&h01, *(uint32_t*)&h23);
        *(uint2*)(out_lo + off) = make_uint2(*(uint32_t*)&l01, *(uint32_t*)&l23);
    }
}

// ---------------------------------------------------------------------------
// Weight prep: W[K,N] fp32 -> transposed single fp16 [N,K]
// ---------------------------------------------------------------------------
__global__ __launch_bounds__(256) void wconv_kernel(
    const float* __restrict__ W, int K, int N, __half* __restrict__ Wh)
{
    __shared__ float t[32][33];
    const int n0 = blockIdx.x * 32;
    const int k0 = blockIdx.y * 32;
    const int tx = threadIdx.x, ty = threadIdx.y;

    #pragma unroll
    for (int i = 0; i < 4; i++)
        t[ty + i * 8][tx] = W[(size_t)(k0 + ty + i * 8) * N + n0 + tx];
    __syncthreads();

    #pragma unroll
    for (int i = 0; i < 4; i++) {
        const int n = n0 + ty + i * 8;
        const int k = k0 + tx;
        Wh[(size_t)n * K + k] = __float2half_rn(t[tx][ty + i * 8]);
    }
}

// ---------------------------------------------------------------------------
// fp16 2-term GEMM on mma.sync: C = relu((Ahi + Alo) @ B^T + bias)
// A: hi/lo fp16 [M,K] row-major. B: fp16 [1024,K] K-major.
// 128x128 CTA tile, 8 warps (2 M x 4 N), warp tile 64x32, m16n8k16.
// 3-stage cp.async pipeline, K-chunk = 64 halves (128B rows, SW128 swizzle).
// ---------------------------------------------------------------------------
#define STAGE_BYTES 49152
#define T_AHI 0
#define T_ALO 16384
#define T_B   32768

__device__ __forceinline__ void load_chunk(
    uint32_t sbase, int c, int tid, int m0, int n0, int K,
    const __half* Ahi, const __half* Alo, const __half* B)
{
    const int r0  = tid >> 3;      // 0..31
    const int seg = tid & 7;       // 16B segment of a 128B row
    const uint32_t st = sbase + (uint32_t)(c % 3) * STAGE_BYTES;
    const size_t koff = (size_t)c * 64 + seg * 8;
    #pragma unroll
    for (int i = 0; i < 4; i++) {
        const int row = r0 + i * 32;
        const uint32_t sw = swz128((uint32_t)(row * 128 + seg * 16));
        cp16(st + T_AHI + sw, Ahi + (size_t)(m0 + row) * K + koff);
        cp16(st + T_ALO + sw, Alo + (size_t)(m0 + row) * K + koff);
        cp16(st + T_B   + sw, B   + (size_t)(n0 + row) * K + koff);
    }
    cp_commit();
}

__global__ __launch_bounds__(256) void gemm_fp16x2(
    int K, int nchunks,
    const __half* __restrict__ Ahi, const __half* __restrict__ Alo,
    const __half* __restrict__ B,
    const float* __restrict__ bias,
    float* __restrict__ Cf, __half* __restrict__ Chi, __half* __restrict__ Clo)
{
    extern __shared__ __align__(1024) char smem[];
    __shared__ float s_bias[128];

    const int tid  = threadIdx.x;
    const int wid  = tid >> 5;
    const int lane = tid & 31;
    const int m0 = blockIdx.y * 128;
    const int n0 = blockIdx.x * 128;
    const int wm = (wid >> 2) * 64;
    const int wn = (wid & 3) * 32;

    const uint32_t sbase = smem_u32(smem);
    if (tid < 128) s_bias[tid] = bias[n0 + tid];

    // Preload 3 stages
    load_chunk(sbase, 0, tid, m0, n0, K, Ahi, Alo, B);
    load_chunk(sbase, 1, tid, m0, n0, K, Ahi, Alo, B);
    load_chunk(sbase, 2, tid, m0, n0, K, Ahi, Alo, B);

    float acc[4][4][4];
    #pragma unroll
    for (int i = 0; i < 4; i++)
        #pragma unroll
        for (int j = 0; j < 4; j++)
            #pragma unroll
            for (int q = 0; q < 4; q++) acc[i][j][q] = 0.0f;

    for (int c = 0; c < nchunks; c++) {
        cp_wait2();
        __syncthreads();

        const uint32_t st = sbase + (uint32_t)(c % 3) * STAGE_BYTES;

        #pragma unroll
        for (int ks = 0; ks < 4; ks++) {
            const uint32_t kb = ks * 32;

            uint32_t bf[4][2];
            #pragma unroll
            for (int nt = 0; nt < 4; nt++) {
                const uint32_t off = swz128(
                    (uint32_t)((wn + nt * 8 + (lane & 7)) * 128) + kb + ((lane >> 3) & 1) * 16);
                ldsm_x2(bf[nt], st + T_B + off);
            }

            #pragma unroll
            for (int mt = 0; mt < 4; mt++) {
                const uint32_t aoff = swz128(
                    (uint32_t)((wm + mt * 16 + (lane & 15)) * 128) + kb + ((lane >> 4) & 1) * 16);
                uint32_t ah[4], al[4];
                ldsm_x4(ah, st + T_AHI + aoff);
                ldsm_x4(al, st + T_ALO + aoff);
                #pragma unroll
                for (int nt = 0; nt < 4; nt++) {
                    mma16816(acc[mt][nt], ah, bf[nt]);
                    mma16816(acc[mt][nt], al, bf[nt]);
                }
            }
        }

        __syncthreads();
        if (c + 3 < nchunks)
            load_chunk(sbase, c + 3, tid, m0, n0, K, Ahi, Alo, B);
    }

    // Epilogue
    const int rbase = m0 + wm + (lane >> 2);
    const int cloc0 = wn + (lane & 3) * 2;
    #pragma unroll
    for (int mt = 0; mt < 4; mt++) {
        #pragma unroll
        for (int half = 0; half < 2; half++) {
            const int row = rbase + mt * 16 + half * 8;
            #pragma unroll
            for (int nt = 0; nt < 4; nt++) {
                const int cl = cloc0 + nt * 8;
                float v0 = fmaxf(acc[mt][nt][half * 2 + 0] + s_bias[cl + 0], 0.0f);
                float v1 = fmaxf(acc[mt][nt][half * 2 + 1] + s_bias[cl + 1], 0.0f);
                const size_t off = (size_t)row * D_ROUTE + n0 + cl;
                if (Cf) {
                    *(float2*)(Cf + off) = make_float2(v0, v1);
                } else {
                    __half h0 = __float2half_rn(v0);
                    __half h1 = __float2half_rn(v1);
                    __half l0 = __float2half_rn(v0 - __half2float(h0));
                    __half l1 = __float2half_rn(v1 - __half2float(h1));
                    __half2 hp = __halves2half2(h0, h1);
                    __half2 lp = __halves2half2(l0, l1);
                    *(uint32_t*)(Chi + off) = *(uint32_t*)&hp;
                    *(uint32_t*)(Clo + off) = *(uint32_t*)&lp;
                }
            }
        }
    }
}

// ---------------------------------------------------------------------------
// kernel_launch
// Inputs: graph_embedding, locations_idx, W0, b0, W1, b1, W2, b2
// ---------------------------------------------------------------------------
extern "C" void kernel_launch(void* const* d_in, const int* in_sizes, int n_in,
                              void* d_out, int out_size)
{
    const float* ge  = (const float*)d_in[0];
    const void*  idx = d_in[1];
    const float* W0  = (const float*)d_in[2];
    const float* b0  = (const float*)d_in[3];
    const float* W1  = (const float*)d_in[4];
    const float* b1  = (const float*)d_in[5];
    const float* W2  = (const float*)d_in[6];
    const float* b2  = (const float*)d_in[7];
    float* out = (float*)d_out;

    __half *ahi, *alo, *bhi, *blo, *w;
    cudaGetSymbolAddress((void**)&ahi, g_ahi);
    cudaGetSymbolAddress((void**)&alo, g_alo);
    cudaGetSymbolAddress((void**)&bhi, g_bhi);
    cudaGetSymbolAddress((void**)&blo, g_blo);
    cudaGetSymbolAddress((void**)&w,   g_w);

    const int smem_bytes = 3 * STAGE_BYTES;   // 144 KB
    cudaFuncSetAttribute(gemm_fp16x2, cudaFuncAttributeMaxDynamicSharedMemorySize, smem_bytes);

    // 0. index dtype detection
    detect_init_kernel<<<1, 1>>>();
    detect_idx_kernel<<<256, 256>>>((const unsigned int*)idx);

    // 1. weight prep (transpose + fp16 round)
    {
        dim3 blk(32, 8);
        wconv_kernel<<<dim3(1024 / 32, 512 / 32),  blk>>>(W0, 512,  1024, w + W0_OFF);
        wconv_kernel<<<dim3(1024 / 32, 1024 / 32), blk>>>(W1, 1024, 1024, w + W1_OFF);
        wconv_kernel<<<dim3(1024 / 32, 1024 / 32), blk>>>(W2, 1024, 1024, w + W2_OFF);
    }

    // 2. gather + max -> fp16 hi/lo activations (stride 512)
    gather_max_kernel<<<N_ROUTES, 256>>>(ge, (const int*)idx, (const long long*)idx, ahi, alo);

    // 3. three GEMM layers
    dim3 grid(D_ROUTE / 128, N_ROUTES / 128);   // (8, 128)
    gemm_fp16x2<<<grid, 256, smem_bytes>>>(512, 8,  ahi, alo, w + W0_OFF, b0,
                                           nullptr, bhi, blo);
    gemm_fp16x2<<<grid, 256, smem_bytes>>>(1024, 16, bhi, blo, w + W1_OFF, b1,
                                           nullptr, ahi, alo);
    gemm_fp16x2<<<grid, 256, smem_bytes>>>(1024, 16, ahi, alo, w + W2_OFF, b2,
                                           out, nullptr, nullptr);
}

// round 6
// speedup vs baseline: 5.7263x; 1.4360x over previous
#include <cuda_runtime.h>
#include <cuda_fp16.h>
#include <cstdint>

// Problem constants
#define N_ROUTES  16384
#define ROUTE_LEN 32
#define D_GRAPH   512
#define D_ROUTE   1024

// ---------------------------------------------------------------------------
// Device scratch (allocation-free). Activations ping-pong as single fp16.
// ---------------------------------------------------------------------------
__device__ __align__(256) __half g_actA[(size_t)N_ROUTES * D_ROUTE];
__device__ __align__(256) __half g_actB[(size_t)N_ROUTES * D_ROUTE];
#define W0_OFF 0
#define W1_OFF (1024*512)
#define W2_OFF (1024*512 + 1024*1024)
#define W_ELEMS (1024*512 + 1024*1024 + 1024*1024)
__device__ __align__(256) __half g_w[W_ELEMS];
__device__ int g_idx_is_i32;

// ---------------------------------------------------------------------------
// Helpers
// ---------------------------------------------------------------------------
__device__ __forceinline__ uint32_t swz128(uint32_t b) { return b ^ ((b >> 3) & 0x70); }

__device__ __forceinline__ uint32_t smem_u32(const void* p) {
    uint32_t a;
    asm("{ .reg .u64 t; cvta.to.shared.u64 t, %1; cvt.u32.u64 %0, t; }" : "=r"(a) : "l"(p));
    return a;
}

__device__ __forceinline__ void cp16(uint32_t dst, const void* src) {
    asm volatile("cp.async.cg.shared.global [%0], [%1], 16;" :: "r"(dst), "l"(src) : "memory");
}
__device__ __forceinline__ void cp_commit() { asm volatile("cp.async.commit_group;" ::: "memory"); }
__device__ __forceinline__ void cp_wait2() { asm volatile("cp.async.wait_group 2;" ::: "memory"); }

__device__ __forceinline__ void ldsm_x4(uint32_t* r, uint32_t addr) {
    asm volatile("ldmatrix.sync.aligned.m8n8.x4.shared.b16 {%0,%1,%2,%3}, [%4];"
                 : "=r"(r[0]), "=r"(r[1]), "=r"(r[2]), "=r"(r[3]) : "r"(addr));
}
__device__ __forceinline__ void ldsm_x2(uint32_t* r, uint32_t addr) {
    asm volatile("ldmatrix.sync.aligned.m8n8.x2.shared.b16 {%0,%1}, [%2];"
                 : "=r"(r[0]), "=r"(r[1]) : "r"(addr));
}

__device__ __forceinline__ void mma16816(float* d, const uint32_t* a, const uint32_t* b) {
    asm volatile(
        "mma.sync.aligned.m16n8k16.row.col.f32.f16.f16.f32 "
        "{%0,%1,%2,%3}, {%4,%5,%6,%7}, {%8,%9}, {%0,%1,%2,%3};"
        : "+f"(d[0]), "+f"(d[1]), "+f"(d[2]), "+f"(d[3])
        : "r"(a[0]), "r"(a[1]), "r"(a[2]), "r"(a[3]), "r"(b[0]), "r"(b[1]));
}

// ---------------------------------------------------------------------------
// Index dtype detection (int32 vs int64 layout).
// ---------------------------------------------------------------------------
__global__ void detect_init_kernel() { g_idx_is_i32 = 0; }

__global__ __launch_bounds__(256) void detect_idx_kernel(const unsigned int* __restrict__ w) {
    const int n_words = N_ROUTES * ROUTE_LEN;
    int found = 0;
    for (int j = (blockIdx.x * blockDim.x + threadIdx.x) * 2 + 1;
         j < n_words; j += gridDim.x * blockDim.x * 2) {
        if (w[j] != 0u) { found = 1; break; }
    }
    if (found) atomicOr(&g_idx_is_i32, 1);
}

// ---------------------------------------------------------------------------
// Gather + max -> single fp16. 256 threads/route, 2 halves via SMEM combine.
// ---------------------------------------------------------------------------
__global__ __launch_bounds__(256) void gather_max_kernel(
    const float* __restrict__ ge,
    const int* __restrict__ idx32,
    const long long* __restrict__ idx64,
    __half* __restrict__ out)
{
    const int r = blockIdx.x;
    __shared__ int s_idx[ROUTE_LEN];
    __shared__ float4 s_red[128];

    if (threadIdx.x < ROUTE_LEN) {
        int v;
        if (g_idx_is_i32) v = idx32[(size_t)r * ROUTE_LEN + threadIdx.x];
        else              v = (int)idx64[(size_t)r * ROUTE_LEN + threadIdx.x];
        s_idx[threadIdx.x] = v;
    }
    __syncthreads();

    const int c    = threadIdx.x & 127;
    const int half = threadIdx.x >> 7;
    float4 m = make_float4(-3.4e38f, -3.4e38f, -3.4e38f, -3.4e38f);

    #pragma unroll 16
    for (int l = half * 16; l < half * 16 + 16; l++) {
        const float4* row = (const float4*)(ge + (size_t)s_idx[l] * D_GRAPH);
        float4 v = __ldg(row + c);
        m.x = fmaxf(m.x, v.x); m.y = fmaxf(m.y, v.y);
        m.z = fmaxf(m.z, v.z); m.w = fmaxf(m.w, v.w);
    }

    if (half == 1) s_red[c] = m;
    __syncthreads();
    if (half == 0) {
        float4 o = s_red[c];
        m.x = fmaxf(m.x, o.x); m.y = fmaxf(m.y, o.y);
        m.z = fmaxf(m.z, o.z); m.w = fmaxf(m.w, o.w);

        __half2 h01 = __halves2half2(__float2half_rn(m.x), __float2half_rn(m.y));
        __half2 h23 = __halves2half2(__float2half_rn(m.z), __float2half_rn(m.w));
        *(uint2*)(out + (size_t)r * D_GRAPH + c * 4) =
            make_uint2(*(uint32_t*)&h01, *(uint32_t*)&h23);
    }
}

// ---------------------------------------------------------------------------
// Weight prep: W[K,N] fp32 -> transposed fp16 [N,K]
// ---------------------------------------------------------------------------
__global__ __launch_bounds__(256) void wconv_kernel(
    const float* __restrict__ W, int K, int N, __half* __restrict__ Wh)
{
    __shared__ float t[32][33];
    const int n0 = blockIdx.x * 32;
    const int k0 = blockIdx.y * 32;
    const int tx = threadIdx.x, ty = threadIdx.y;

    #pragma unroll
    for (int i = 0; i < 4; i++)
        t[ty + i * 8][tx] = W[(size_t)(k0 + ty + i * 8) * N + n0 + tx];
    __syncthreads();

    #pragma unroll
    for (int i = 0; i < 4; i++) {
        const int n = n0 + ty + i * 8;
        const int k = k0 + tx;
        Wh[(size_t)n * K + k] = __float2half_rn(t[tx][ty + i * 8]);
    }
}

// ---------------------------------------------------------------------------
// fp16 GEMM on mma.sync: C = relu(A @ B^T + bias)
// A: fp16 [M,K] row-major. B: fp16 [1024,K] K-major.
// 256x128 CTA tile, 8 warps (4 M x 2 N), warp tile 64x64, m16n8k16.
// 3-stage cp.async pipeline, K-chunk = 64 halves (128B rows, SW128 swizzle).
// ---------------------------------------------------------------------------
#define STAGE_BYTES 49152
#define T_A 0
#define T_B 32768

__device__ __forceinline__ void load_chunk(
    uint32_t sbase, int c, int tid, int m0, int n0, int K,
    const __half* A, const __half* B)
{
    const int r0  = tid >> 3;      // 0..31
    const int seg = tid & 7;       // 16B segment of a 128B row
    const uint32_t st = sbase + (uint32_t)(c % 3) * STAGE_BYTES;
    const size_t koff = (size_t)c * 64 + seg * 8;
    #pragma unroll
    for (int i = 0; i < 8; i++) {
        const int row = r0 + i * 32;
        const uint32_t sw = swz128((uint32_t)(row * 128 + seg * 16));
        cp16(st + T_A + sw, A + (size_t)(m0 + row) * K + koff);
        if (i < 4)
            cp16(st + T_B + sw, B + (size_t)(n0 + row) * K + koff);
    }
    cp_commit();
}

__global__ __launch_bounds__(256) void gemm_fp16(
    int K, int nchunks,
    const __half* __restrict__ A, const __half* __restrict__ B,
    const float* __restrict__ bias,
    float* __restrict__ Cf, __half* __restrict__ Ch)
{
    extern __shared__ __align__(1024) char smem[];
    __shared__ float s_bias[128];

    const int tid  = threadIdx.x;
    const int wid  = tid >> 5;
    const int lane = tid & 31;
    const int m0 = blockIdx.y * 256;
    const int n0 = blockIdx.x * 128;
    const int wm = (wid >> 1) * 64;   // 0/64/128/192
    const int wn = (wid & 1) * 64;    // 0/64

    const uint32_t sbase = smem_u32(smem);
    if (tid < 128) s_bias[tid] = bias[n0 + tid];

    // Preload 3 stages
    load_chunk(sbase, 0, tid, m0, n0, K, A, B);
    load_chunk(sbase, 1, tid, m0, n0, K, A, B);
    load_chunk(sbase, 2, tid, m0, n0, K, A, B);

    float acc[4][8][4];
    #pragma unroll
    for (int i = 0; i < 4; i++)
        #pragma unroll
        for (int j = 0; j < 8; j++)
            #pragma unroll
            for (int q = 0; q < 4; q++) acc[i][j][q] = 0.0f;

    for (int c = 0; c < nchunks; c++) {
        cp_wait2();
        __syncthreads();

        const uint32_t st = sbase + (uint32_t)(c % 3) * STAGE_BYTES;

        #pragma unroll
        for (int ks = 0; ks < 4; ks++) {
            const uint32_t kb = ks * 32;

            uint32_t bf[8][2];
            #pragma unroll
            for (int nt = 0; nt < 8; nt++) {
                const uint32_t off = swz128(
                    (uint32_t)((wn + nt * 8 + (lane & 7)) * 128) + kb + ((lane >> 3) & 1) * 16);
                ldsm_x2(bf[nt], st + T_B + off);
            }

            #pragma unroll
            for (int mt = 0; mt < 4; mt++) {
                const uint32_t aoff = swz128(
                    (uint32_t)((wm + mt * 16 + (lane & 15)) * 128) + kb + ((lane >> 4) & 1) * 16);
                uint32_t af[4];
                ldsm_x4(af, st + T_A + aoff);
                #pragma unroll
                for (int nt = 0; nt < 8; nt++)
                    mma16816(acc[mt][nt], af, bf[nt]);
            }
        }

        __syncthreads();
        if (c + 3 < nchunks)
            load_chunk(sbase, c + 3, tid, m0, n0, K, A, B);
    }

    // Epilogue
    const int rbase = m0 + wm + (lane >> 2);
    const int cloc0 = wn + (lane & 3) * 2;
    #pragma unroll
    for (int mt = 0; mt < 4; mt++) {
        #pragma unroll
        for (int half = 0; half < 2; half++) {
            const int row = rbase + mt * 16 + half * 8;
            #pragma unroll
            for (int nt = 0; nt < 8; nt++) {
                const int cl = cloc0 + nt * 8;
                float v0 = fmaxf(acc[mt][nt][half * 2 + 0] + s_bias[cl + 0], 0.0f);
                float v1 = fmaxf(acc[mt][nt][half * 2 + 1] + s_bias[cl + 1], 0.0f);
                const size_t off = (size_t)row * D_ROUTE + n0 + cl;
                if (Cf) {
                    *(float2*)(Cf + off) = make_float2(v0, v1);
                } else {
                    __half2 hp = __halves2half2(__float2half_rn(v0), __float2half_rn(v1));
                    *(uint32_t*)(Ch + off) = *(uint32_t*)&hp;
                }
            }
        }
    }
}

// ---------------------------------------------------------------------------
// kernel_launch
// Inputs: graph_embedding, locations_idx, W0, b0, W1, b1, W2, b2
// ---------------------------------------------------------------------------
extern "C" void kernel_launch(void* const* d_in, const int* in_sizes, int n_in,
                              void* d_out, int out_size)
{
    const float* ge  = (const float*)d_in[0];
    const void*  idx = d_in[1];
    const float* W0  = (const float*)d_in[2];
    const float* b0  = (const float*)d_in[3];
    const float* W1  = (const float*)d_in[4];
    const float* b1  = (const float*)d_in[5];
    const float* W2  = (const float*)d_in[6];
    const float* b2  = (const float*)d_in[7];
    float* out = (float*)d_out;

    __half *actA, *actB, *w;
    cudaGetSymbolAddress((void**)&actA, g_actA);
    cudaGetSymbolAddress((void**)&actB, g_actB);
    cudaGetSymbolAddress((void**)&w,    g_w);

    const int smem_bytes = 3 * STAGE_BYTES;   // 144 KB
    cudaFuncSetAttribute(gemm_fp16, cudaFuncAttributeMaxDynamicSharedMemorySize, smem_bytes);

    // 0. index dtype detection
    detect_init_kernel<<<1, 1>>>();
    detect_idx_kernel<<<256, 256>>>((const unsigned int*)idx);

    // 1. weight prep (transpose + fp16 round)
    {
        dim3 blk(32, 8);
        wconv_kernel<<<dim3(1024 / 32, 512 / 32),  blk>>>(W0, 512,  1024, w + W0_OFF);
        wconv_kernel<<<dim3(1024 / 32, 1024 / 32), blk>>>(W1, 1024, 1024, w + W1_OFF);
        wconv_kernel<<<dim3(1024 / 32, 1024 / 32), blk>>>(W2, 1024, 1024, w + W2_OFF);
    }

    // 2. gather + max -> fp16 activations (stride 512)
    gather_max_kernel<<<N_ROUTES, 256>>>(ge, (const int*)idx, (const long long*)idx, actA);

    // 3. three GEMM layers
    dim3 grid(D_ROUTE / 128, N_ROUTES / 256);   // (8, 64)
    gemm_fp16<<<grid, 256, smem_bytes>>>(512,  8,  actA, w + W0_OFF, b0, nullptr, actB);
    gemm_fp16<<<grid, 256, smem_bytes>>>(1024, 16, actB, w + W1_OFF, b1, nullptr, actA);
    gemm_fp16<<<grid, 256, smem_bytes>>>(1024, 16, actA, w + W2_OFF, b2, out, nullptr);
}

// round 7
// speedup vs baseline: 6.1792x; 1.0791x over previous
#include <cuda_runtime.h>
#include <cuda_fp16.h>
#include <cstdint>

// Problem constants
#define N_ROUTES  16384
#define ROUTE_LEN 32
#define D_GRAPH   512
#define D_ROUTE   1024

// ---------------------------------------------------------------------------
// Device scratch (allocation-free). Activations ping-pong as single fp16.
// ---------------------------------------------------------------------------
__device__ __align__(256) __half g_actA[(size_t)N_ROUTES * D_ROUTE];
__device__ __align__(256) __half g_actB[(size_t)N_ROUTES * D_ROUTE];
#define W0_OFF 0
#define W1_OFF (1024*512)
#define W2_OFF (1024*512 + 1024*1024)
#define W_ELEMS (1024*512 + 1024*1024 + 1024*1024)
__device__ __align__(256) __half g_w[W_ELEMS];
__device__ int g_idx_is_i32;

// ---------------------------------------------------------------------------
// Helpers
// ---------------------------------------------------------------------------
__device__ __forceinline__ uint32_t swz128(uint32_t b) { return b ^ ((b >> 3) & 0x70); }

__device__ __forceinline__ uint32_t smem_u32(const void* p) {
    uint32_t a;
    asm("{ .reg .u64 t; cvta.to.shared.u64 t, %1; cvt.u32.u64 %0, t; }" : "=r"(a) : "l"(p));
    return a;
}

__device__ __forceinline__ void cp16(uint32_t dst, const void* src) {
    asm volatile("cp.async.cg.shared.global [%0], [%1], 16;" :: "r"(dst), "l"(src) : "memory");
}
__device__ __forceinline__ void cp_commit() { asm volatile("cp.async.commit_group;" ::: "memory"); }
__device__ __forceinline__ void cp_wait2() { asm volatile("cp.async.wait_group 2;" ::: "memory"); }

__device__ __forceinline__ void ldsm_x4(uint32_t* r, uint32_t addr) {
    asm volatile("ldmatrix.sync.aligned.m8n8.x4.shared.b16 {%0,%1,%2,%3}, [%4];"
                 : "=r"(r[0]), "=r"(r[1]), "=r"(r[2]), "=r"(r[3]) : "r"(addr));
}

__device__ __forceinline__ void mma16816(float* d, const uint32_t* a, const uint32_t* b) {
    asm volatile(
        "mma.sync.aligned.m16n8k16.row.col.f32.f16.f16.f32 "
        "{%0,%1,%2,%3}, {%4,%5,%6,%7}, {%8,%9}, {%0,%1,%2,%3};"
        : "+f"(d[0]), "+f"(d[1]), "+f"(d[2]), "+f"(d[3])
        : "r"(a[0]), "r"(a[1]), "r"(a[2]), "r"(a[3]), "r"(b[0]), "r"(b[1]));
}

// ---------------------------------------------------------------------------
// Index dtype detection (int32 vs int64 layout).
// ---------------------------------------------------------------------------
__global__ void detect_init_kernel() { g_idx_is_i32 = 0; }

__global__ __launch_bounds__(256) void detect_idx_kernel(const unsigned int* __restrict__ w) {
    const int n_words = N_ROUTES * ROUTE_LEN;
    int found = 0;
    for (int j = (blockIdx.x * blockDim.x + threadIdx.x) * 2 + 1;
         j < n_words; j += gridDim.x * blockDim.x * 2) {
        if (w[j] != 0u) { found = 1; break; }
    }
    if (found) atomicOr(&g_idx_is_i32, 1);
}

// ---------------------------------------------------------------------------
// Gather + max -> single fp16. 256 threads/route, 2 halves via SMEM combine.
// ---------------------------------------------------------------------------
__global__ __launch_bounds__(256) void gather_max_kernel(
    const float* __restrict__ ge,
    const int* __restrict__ idx32,
    const long long* __restrict__ idx64,
    __half* __restrict__ out)
{
    const int r = blockIdx.x;
    __shared__ int s_idx[ROUTE_LEN];
    __shared__ float4 s_red[128];

    if (threadIdx.x < ROUTE_LEN) {
        int v;
        if (g_idx_is_i32) v = idx32[(size_t)r * ROUTE_LEN + threadIdx.x];
        else              v = (int)idx64[(size_t)r * ROUTE_LEN + threadIdx.x];
        s_idx[threadIdx.x] = v;
    }
    __syncthreads();

    const int c    = threadIdx.x & 127;
    const int half = threadIdx.x >> 7;
    float4 m = make_float4(-3.4e38f, -3.4e38f, -3.4e38f, -3.4e38f);

    #pragma unroll 16
    for (int l = half * 16; l < half * 16 + 16; l++) {
        const float4* row = (const float4*)(ge + (size_t)s_idx[l] * D_GRAPH);
        float4 v = __ldg(row + c);
        m.x = fmaxf(m.x, v.x); m.y = fmaxf(m.y, v.y);
        m.z = fmaxf(m.z, v.z); m.w = fmaxf(m.w, v.w);
    }

    if (half == 1) s_red[c] = m;
    __syncthreads();
    if (half == 0) {
        float4 o = s_red[c];
        m.x = fmaxf(m.x, o.x); m.y = fmaxf(m.y, o.y);
        m.z = fmaxf(m.z, o.z); m.w = fmaxf(m.w, o.w);

        __half2 h01 = __halves2half2(__float2half_rn(m.x), __float2half_rn(m.y));
        __half2 h23 = __halves2half2(__float2half_rn(m.z), __float2half_rn(m.w));
        *(uint2*)(out + (size_t)r * D_GRAPH + c * 4) =
            make_uint2(*(uint32_t*)&h01, *(uint32_t*)&h23);
    }
}

// ---------------------------------------------------------------------------
// Weight prep: W[K,N] fp32 -> transposed fp16 [N,K]
// ---------------------------------------------------------------------------
__global__ __launch_bounds__(256) void wconv_kernel(
    const float* __restrict__ W, int K, int N, __half* __restrict__ Wh)
{
    __shared__ float t[32][33];
    const int n0 = blockIdx.x * 32;
    const int k0 = blockIdx.y * 32;
    const int tx = threadIdx.x, ty = threadIdx.y;

    #pragma unroll
    for (int i = 0; i < 4; i++)
        t[ty + i * 8][tx] = W[(size_t)(k0 + ty + i * 8) * N + n0 + tx];
    __syncthreads();

    #pragma unroll
    for (int i = 0; i < 4; i++) {
        const int n = n0 + ty + i * 8;
        const int k = k0 + tx;
        Wh[(size_t)n * K + k] = __float2half_rn(t[tx][ty + i * 8]);
    }
}

// ---------------------------------------------------------------------------
// fp16 GEMM on mma.sync: C = relu(A @ B^T + bias)
// A: fp16 [M,K] row-major. B: fp16 [1024,K] K-major.
// 256x128 CTA tile, 8 warps (4 M x 2 N), warp tile 64x64, m16n8k16.
// 4-stage cp.async pipeline, K-chunk = 64 halves (128B rows, SW128 swizzle),
// ONE __syncthreads per chunk (stage c+3 never aliases stage c with 4 stages).
// ---------------------------------------------------------------------------
#define STAGE_BYTES 49152
#define T_A 0
#define T_B 32768

__device__ __forceinline__ void load_chunk(
    uint32_t sbase, int c, int tid, int m0, int n0, int K,
    const __half* A, const __half* B)
{
    const int r0  = tid >> 3;      // 0..31
    const int seg = tid & 7;       // 16B segment of a 128B row
    const uint32_t st = sbase + (uint32_t)(c & 3) * STAGE_BYTES;
    const size_t koff = (size_t)c * 64 + seg * 8;
    #pragma unroll
    for (int i = 0; i < 8; i++) {
        const int row = r0 + i * 32;
        const uint32_t sw = swz128((uint32_t)(row * 128 + seg * 16));
        cp16(st + T_A + sw, A + (size_t)(m0 + row) * K + koff);
        if (i < 4)
            cp16(st + T_B + sw, B + (size_t)(n0 + row) * K + koff);
    }
    cp_commit();
}

__global__ __launch_bounds__(256) void gemm_fp16(
    int K, int nchunks,
    const __half* __restrict__ A, const __half* __restrict__ B,
    const float* __restrict__ bias,
    float* __restrict__ Cf, __half* __restrict__ Ch)
{
    extern __shared__ __align__(1024) char smem[];
    __shared__ float s_bias[128];

    const int tid  = threadIdx.x;
    const int wid  = tid >> 5;
    const int lane = tid & 31;
    const int m0 = blockIdx.y * 256;
    const int n0 = blockIdx.x * 128;
    const int wm = (wid >> 1) * 64;   // 0/64/128/192
    const int wn = (wid & 1) * 64;    // 0/64

    const uint32_t sbase = smem_u32(smem);
    if (tid < 128) s_bias[tid] = bias[n0 + tid];

    // Preload 3 stages (4th stage stays free for single-sync rotation)
    load_chunk(sbase, 0, tid, m0, n0, K, A, B);
    load_chunk(sbase, 1, tid, m0, n0, K, A, B);
    load_chunk(sbase, 2, tid, m0, n0, K, A, B);

    float acc[4][8][4];
    #pragma unroll
    for (int i = 0; i < 4; i++)
        #pragma unroll
        for (int j = 0; j < 8; j++)
            #pragma unroll
            for (int q = 0; q < 4; q++) acc[i][j][q] = 0.0f;

    for (int c = 0; c < nchunks; c++) {
        cp_wait2();
        __syncthreads();   // all warps done computing chunk c-1; stage (c+3)&3 is free

        const uint32_t st = sbase + (uint32_t)(c & 3) * STAGE_BYTES;

        #pragma unroll
        for (int ks = 0; ks < 4; ks++) {
            const uint32_t kb = ks * 32;

            // B fragments: ldsm_x4 loads two adjacent n-tiles (2 k-halves each)
            uint32_t bf[8][2];
            #pragma unroll
            for (int ntp = 0; ntp < 4; ntp++) {
                const uint32_t off = swz128(
                    (uint32_t)((wn + ntp * 16 + ((lane >> 4) & 1) * 8 + (lane & 7)) * 128)
                    + kb + ((lane >> 3) & 1) * 16);
                uint32_t r[4];
                ldsm_x4(r, st + T_B + off);
                bf[ntp * 2 + 0][0] = r[0]; bf[ntp * 2 + 0][1] = r[1];
                bf[ntp * 2 + 1][0] = r[2]; bf[ntp * 2 + 1][1] = r[3];
            }

            #pragma unroll
            for (int mt = 0; mt < 4; mt++) {
                const uint32_t aoff = swz128(
                    (uint32_t)((wm + mt * 16 + (lane & 15)) * 128) + kb + ((lane >> 4) & 1) * 16);
                uint32_t af[4];
                ldsm_x4(af, st + T_A + aoff);
                #pragma unroll
                for (int nt = 0; nt < 8; nt++)
                    mma16816(acc[mt][nt], af, bf[nt]);
            }
        }

        if (c + 3 < nchunks)
            load_chunk(sbase, c + 3, tid, m0, n0, K, A, B);
    }

    // Epilogue
    const int rbase = m0 + wm + (lane >> 2);
    const int cloc0 = wn + (lane & 3) * 2;
    #pragma unroll
    for (int mt = 0; mt < 4; mt++) {
        #pragma unroll
        for (int half = 0; half < 2; half++) {
            const int row = rbase + mt * 16 + half * 8;
            #pragma unroll
            for (int nt = 0; nt < 8; nt++) {
                const int cl = cloc0 + nt * 8;
                float v0 = fmaxf(acc[mt][nt][half * 2 + 0] + s_bias[cl + 0], 0.0f);
                float v1 = fmaxf(acc[mt][nt][half * 2 + 1] + s_bias[cl + 1], 0.0f);
                const size_t off = (size_t)row * D_ROUTE + n0 + cl;
                if (Cf) {
                    *(float2*)(Cf + off) = make_float2(v0, v1);
                } else {
                    __half2 hp = __halves2half2(__float2half_rn(v0), __float2half_rn(v1));
                    *(uint32_t*)(Ch + off) = *(uint32_t*)&hp;
                }
            }
        }
    }
}

// ---------------------------------------------------------------------------
// kernel_launch
// Inputs: graph_embedding, locations_idx, W0, b0, W1, b1, W2, b2
// ---------------------------------------------------------------------------
extern "C" void kernel_launch(void* const* d_in, const int* in_sizes, int n_in,
                              void* d_out, int out_size)
{
    const float* ge  = (const float*)d_in[0];
    const void*  idx = d_in[1];
    const float* W0  = (const float*)d_in[2];
    const float* b0  = (const float*)d_in[3];
    const float* W1  = (const float*)d_in[4];
    const float* b1  = (const float*)d_in[5];
    const float* W2  = (const float*)d_in[6];
    const float* b2  = (const float*)d_in[7];
    float* out = (float*)d_out;

    __half *actA, *actB, *w;
    cudaGetSymbolAddress((void**)&actA, g_actA);
    cudaGetSymbolAddress((void**)&actB, g_actB);
    cudaGetSymbolAddress((void**)&w,    g_w);

    const int smem_bytes = 4 * STAGE_BYTES;   // 192 KB
    cudaFuncSetAttribute(gemm_fp16, cudaFuncAttributeMaxDynamicSharedMemorySize, smem_bytes);

    // 0. index dtype detection
    detect_init_kernel<<<1, 1>>>();
    detect_idx_kernel<<<256, 256>>>((const unsigned int*)idx);

    // 1. weight prep (transpose + fp16 round)
    {
        dim3 blk(32, 8);
        wconv_kernel<<<dim3(1024 / 32, 512 / 32),  blk>>>(W0, 512,  1024, w + W0_OFF);
        wconv_kernel<<<dim3(1024 / 32, 1024 / 32), blk>>>(W1, 1024, 1024, w + W1_OFF);
        wconv_kernel<<<dim3(1024 / 32, 1024 / 32), blk>>>(W2, 1024, 1024, w + W2_OFF);
    }

    // 2. gather + max -> fp16 activations (stride 512)
    gather_max_kernel<<<N_ROUTES, 256>>>(ge, (const int*)idx, (const long long*)idx, actA);

    // 3. three GEMM layers
    dim3 grid(D_ROUTE / 128, N_ROUTES / 256);   // (8, 64)
    gemm_fp16<<<grid, 256, smem_bytes>>>(512,  8,  actA, w + W0_OFF, b0, nullptr, actB);
    gemm_fp16<<<grid, 256, smem_bytes>>>(1024, 16, actB, w + W1_OFF, b1, nullptr, actA);
    gemm_fp16<<<grid, 256, smem_bytes>>>(1024, 16, actA, w + W2_OFF, b2, out, nullptr);
}

// round 8
// speedup vs baseline: 6.6354x; 1.0738x over previous
#include <cuda_runtime.h>
#include <cuda_fp16.h>
#include <cstdint>

// Problem constants
#define N_ROUTES  16384
#define ROUTE_LEN 32
#define D_GRAPH   512
#define D_ROUTE   1024
#define N_NODES   100000

// ---------------------------------------------------------------------------
// Device scratch (allocation-free).
// ---------------------------------------------------------------------------
__device__ __align__(256) __half g_ge16[(size_t)N_NODES * D_GRAPH];   // fp16 table
__device__ __align__(256) __half g_actA[(size_t)N_ROUTES * D_ROUTE];
__device__ __align__(256) __half g_actB[(size_t)N_ROUTES * D_ROUTE];
#define W0_OFF 0
#define W1_OFF (1024*512)
#define W2_OFF (1024*512 + 1024*1024)
#define W_ELEMS (1024*512 + 1024*1024 + 1024*1024)
__device__ __align__(256) __half g_w[W_ELEMS];

// ---------------------------------------------------------------------------
// Helpers
// ---------------------------------------------------------------------------
__device__ __forceinline__ uint32_t swz128(uint32_t b) { return b ^ ((b >> 3) & 0x70); }

__device__ __forceinline__ uint32_t smem_u32(const void* p) {
    uint32_t a;
    asm("{ .reg .u64 t; cvta.to.shared.u64 t, %1; cvt.u32.u64 %0, t; }" : "=r"(a) : "l"(p));
    return a;
}

__device__ __forceinline__ void cp16(uint32_t dst, const void* src) {
    asm volatile("cp.async.cg.shared.global [%0], [%1], 16;" :: "r"(dst), "l"(src) : "memory");
}
__device__ __forceinline__ void cp_commit() { asm volatile("cp.async.commit_group;" ::: "memory"); }
__device__ __forceinline__ void cp_wait2() { asm volatile("cp.async.wait_group 2;" ::: "memory"); }

__device__ __forceinline__ void ldsm_x4(uint32_t* r, uint32_t addr) {
    asm volatile("ldmatrix.sync.aligned.m8n8.x4.shared.b16 {%0,%1,%2,%3}, [%4];"
                 : "=r"(r[0]), "=r"(r[1]), "=r"(r[2]), "=r"(r[3]) : "r"(addr));
}

__device__ __forceinline__ void mma16816(float* d, const uint32_t* a, const uint32_t* b) {
    asm volatile(
        "mma.sync.aligned.m16n8k16.row.col.f32.f16.f16.f32 "
        "{%0,%1,%2,%3}, {%4,%5,%6,%7}, {%8,%9}, {%0,%1,%2,%3};"
        : "+f"(d[0]), "+f"(d[1]), "+f"(d[2]), "+f"(d[3])
        : "r"(a[0]), "r"(a[1]), "r"(a[2]), "r"(a[3]), "r"(b[0]), "r"(b[1]));
}

__device__ __forceinline__ uint4 hmax2x4(uint4 a, uint4 b) {
    __half2* pa = (__half2*)&a;
    __half2* pb = (__half2*)&b;
    uint4 r;
    __half2* pr = (__half2*)&r;
    pr[0] = __hmax2(pa[0], pb[0]);
    pr[1] = __hmax2(pa[1], pb[1]);
    pr[2] = __hmax2(pa[2], pb[2]);
    pr[3] = __hmax2(pa[3], pb[3]);
    return r;
}

// ---------------------------------------------------------------------------
// Table conversion: graph_embedding fp32 -> fp16 (leaves fp16 table hot in L2).
// 8 elements per thread; grid covers 100000*512 exactly (25000 blocks x 256).
// ---------------------------------------------------------------------------
__global__ __launch_bounds__(256) void conv_kernel(
    const float* __restrict__ ge, __half* __restrict__ o)
{
    const size_t i = (size_t)blockIdx.x * 256 + threadIdx.x;   // 8 floats each
    const float4* p = (const float4*)ge;
    float4 a = p[2 * i];
    float4 b = p[2 * i + 1];
    __half2 h0 = __floats2half2_rn(a.x, a.y);
    __half2 h1 = __floats2half2_rn(a.z, a.w);
    __half2 h2 = __floats2half2_rn(b.x, b.y);
    __half2 h3 = __floats2half2_rn(b.z, b.w);
    uint4 u;
    u.x = *(uint32_t*)&h0; u.y = *(uint32_t*)&h1;
    u.z = *(uint32_t*)&h2; u.w = *(uint32_t*)&h3;
    ((uint4*)o)[i] = u;
}

// ---------------------------------------------------------------------------
// Gather + max on the fp16 table, with per-route index-dtype self-detection.
// 256 threads/route: 4 quarters x 8 positions; 64 uint4 column groups.
// Detection: words [r*32, r*32+32) are in-bounds under BOTH layouts.
//   int64 layout: odd words are hi-words of values < 2^31 -> all zero.
//   int32 layout: odd words are random indices -> some nonzero (p_fail ~1e-80).
// ---------------------------------------------------------------------------
__global__ __launch_bounds__(256) void gather_max_kernel(
    const __half* __restrict__ ge16,
    const unsigned int* __restrict__ w,
    __half* __restrict__ out)
{
    const int r = blockIdx.x;
    __shared__ int s_idx[ROUTE_LEN];
    __shared__ uint4 s_red[3][64];

    const int tid = threadIdx.x;
    if (tid < 32) {
        unsigned int odd = w[(size_t)r * 32 + 2 * (tid & 15) + 1];
        int is_i32 = __any_sync(0xFFFFFFFFu, (tid < 16) && odd != 0u);
        int v;
        if (is_i32) v = (int)w[(size_t)r * 32 + tid];
        else        v = (int)w[(size_t)r * 64 + 2 * tid];
        s_idx[tid] = v;
    }
    __syncthreads();

    const int g = tid & 63;    // uint4 column group: cols g*8 .. g*8+7
    const int q = tid >> 6;    // quarter: positions q*8 .. q*8+7

    const uint4* row0 = (const uint4*)(ge16 + (size_t)s_idx[q * 8] * D_GRAPH);
    uint4 acc = __ldg(row0 + g);
    #pragma unroll 7
    for (int l = 1; l < 8; l++) {
        const uint4* row = (const uint4*)(ge16 + (size_t)s_idx[q * 8 + l] * D_GRAPH);
        acc = hmax2x4(acc, __ldg(row + g));
    }

    if (q) s_red[q - 1][g] = acc;
    __syncthreads();
    if (!q) {
        acc = hmax2x4(acc, s_red[0][g]);
        acc = hmax2x4(acc, s_red[1][g]);
        acc = hmax2x4(acc, s_red[2][g]);
        *(uint4*)(out + (size_t)r * D_GRAPH + g * 8) = acc;
    }
}

// ---------------------------------------------------------------------------
// Weight prep: W[K,N] fp32 -> transposed fp16 [N,K]
// ---------------------------------------------------------------------------
__global__ __launch_bounds__(256) void wconv_kernel(
    const float* __restrict__ W, int K, int N, __half* __restrict__ Wh)
{
    __shared__ float t[32][33];
    const int n0 = blockIdx.x * 32;
    const int k0 = blockIdx.y * 32;
    const int tx = threadIdx.x, ty = threadIdx.y;

    #pragma unroll
    for (int i = 0; i < 4; i++)
        t[ty + i * 8][tx] = W[(size_t)(k0 + ty + i * 8) * N + n0 + tx];
    __syncthreads();

    #pragma unroll
    for (int i = 0; i < 4; i++) {
        const int n = n0 + ty + i * 8;
        const int k = k0 + tx;
        Wh[(size_t)n * K + k] = __float2half_rn(t[tx][ty + i * 8]);
    }
}

// ---------------------------------------------------------------------------
// fp16 GEMM on mma.sync: C = relu(A @ B^T + bias)
// 256x128 CTA tile, 8 warps (4 M x 2 N), warp tile 64x64, m16n8k16.
// 4-stage cp.async pipeline, single __syncthreads per chunk.
// ---------------------------------------------------------------------------
#define STAGE_BYTES 49152
#define T_A 0
#define T_B 32768

__device__ __forceinline__ void load_chunk(
    uint32_t sbase, int c, int tid, int m0, int n0, int K,
    const __half* A, const __half* B)
{
    const int r0  = tid >> 3;
    const int seg = tid & 7;
    const uint32_t st = sbase + (uint32_t)(c & 3) * STAGE_BYTES;
    const size_t koff = (size_t)c * 64 + seg * 8;
    #pragma unroll
    for (int i = 0; i < 8; i++) {
        const int row = r0 + i * 32;
        const uint32_t sw = swz128((uint32_t)(row * 128 + seg * 16));
        cp16(st + T_A + sw, A + (size_t)(m0 + row) * K + koff);
        if (i < 4)
            cp16(st + T_B + sw, B + (size_t)(n0 + row) * K + koff);
    }
    cp_commit();
}

__global__ __launch_bounds__(256) void gemm_fp16(
    int K, int nchunks,
    const __half* __restrict__ A, const __half* __restrict__ B,
    const float* __restrict__ bias,
    float* __restrict__ Cf, __half* __restrict__ Ch)
{
    extern __shared__ __align__(1024) char smem[];
    __shared__ float s_bias[128];

    const int tid  = threadIdx.x;
    const int wid  = tid >> 5;
    const int lane = tid & 31;
    const int m0 = blockIdx.y * 256;
    const int n0 = blockIdx.x * 128;
    const int wm = (wid >> 1) * 64;
    const int wn = (wid & 1) * 64;

    const uint32_t sbase = smem_u32(smem);
    if (tid < 128) s_bias[tid] = bias[n0 + tid];

    load_chunk(sbase, 0, tid, m0, n0, K, A, B);
    load_chunk(sbase, 1, tid, m0, n0, K, A, B);
    load_chunk(sbase, 2, tid, m0, n0, K, A, B);

    float acc[4][8][4];
    #pragma unroll
    for (int i = 0; i < 4; i++)
        #pragma unroll
        for (int j = 0; j < 8; j++)
            #pragma unroll
            for (int q = 0; q < 4; q++) acc[i][j][q] = 0.0f;

    for (int c = 0; c < nchunks; c++) {
        cp_wait2();
        __syncthreads();

        const uint32_t st = sbase + (uint32_t)(c & 3) * STAGE_BYTES;

        #pragma unroll
        for (int ks = 0; ks < 4; ks++) {
            const uint32_t kb = ks * 32;

            uint32_t bf[8][2];
            #pragma unroll
            for (int ntp = 0; ntp < 4; ntp++) {
                const uint32_t off = swz128(
                    (uint32_t)((wn + ntp * 16 + ((lane >> 4) & 1) * 8 + (lane & 7)) * 128)
                    + kb + ((lane >> 3) & 1) * 16);
                uint32_t r[4];
                ldsm_x4(r, st + T_B + off);
                bf[ntp * 2 + 0][0] = r[0]; bf[ntp * 2 + 0][1] = r[1];
                bf[ntp * 2 + 1][0] = r[2]; bf[ntp * 2 + 1][1] = r[3];
            }

            #pragma unroll
            for (int mt = 0; mt < 4; mt++) {
                const uint32_t aoff = swz128(
                    (uint32_t)((wm + mt * 16 + (lane & 15)) * 128) + kb + ((lane >> 4) & 1) * 16);
                uint32_t af[4];
                ldsm_x4(af, st + T_A + aoff);
                #pragma unroll
                for (int nt = 0; nt < 8; nt++)
                    mma16816(acc[mt][nt], af, bf[nt]);
            }
        }

        if (c + 3 < nchunks)
            load_chunk(sbase, c + 3, tid, m0, n0, K, A, B);
    }

    // Epilogue
    const int rbase = m0 + wm + (lane >> 2);
    const int cloc0 = wn + (lane & 3) * 2;
    #pragma unroll
    for (int mt = 0; mt < 4; mt++) {
        #pragma unroll
        for (int half = 0; half < 2; half++) {
            const int row = rbase + mt * 16 + half * 8;
            #pragma unroll
            for (int nt = 0; nt < 8; nt++) {
                const int cl = cloc0 + nt * 8;
                float v0 = fmaxf(acc[mt][nt][half * 2 + 0] + s_bias[cl + 0], 0.0f);
                float v1 = fmaxf(acc[mt][nt][half * 2 + 1] + s_bias[cl + 1], 0.0f);
                const size_t off = (size_t)row * D_ROUTE + n0 + cl;
                if (Cf) {
                    *(float2*)(Cf + off) = make_float2(v0, v1);
                } else {
                    __half2 hp = __halves2half2(__float2half_rn(v0), __float2half_rn(v1));
                    *(uint32_t*)(Ch + off) = *(uint32_t*)&hp;
                }
            }
        }
    }
}

// ---------------------------------------------------------------------------
// kernel_launch — ordered so gemm L0 is the 6th launch (ncu -s 5 -c 1 window).
// Inputs: graph_embedding, locations_idx, W0, b0, W1, b1, W2, b2
// ---------------------------------------------------------------------------
extern "C" void kernel_launch(void* const* d_in, const int* in_sizes, int n_in,
                              void* d_out, int out_size)
{
    const float* ge  = (const float*)d_in[0];
    const void*  idx = d_in[1];
    const float* W0  = (const float*)d_in[2];
    const float* b0  = (const float*)d_in[3];
    const float* W1  = (const float*)d_in[4];
    const float* b1  = (const float*)d_in[5];
    const float* W2  = (const float*)d_in[6];
    const float* b2  = (const float*)d_in[7];
    float* out = (float*)d_out;

    __half *ge16, *actA, *actB, *w;
    cudaGetSymbolAddress((void**)&ge16, g_ge16);
    cudaGetSymbolAddress((void**)&actA, g_actA);
    cudaGetSymbolAddress((void**)&actB, g_actB);
    cudaGetSymbolAddress((void**)&w,    g_w);

    const int smem_bytes = 4 * STAGE_BYTES;   // 192 KB
    cudaFuncSetAttribute(gemm_fp16, cudaFuncAttributeMaxDynamicSharedMemorySize, smem_bytes);

    // 1. fp32 -> fp16 table (100000*512 / 8 / 256 = 25000 blocks)
    conv_kernel<<<25000, 256>>>(ge, ge16);

    // 2. gather + max (self-detecting index dtype) -> fp16 activations
    gather_max_kernel<<<N_ROUTES, 256>>>(ge16, (const unsigned int*)idx, actA);

    // 3-5. weight prep
    dim3 blk(32, 8);
    wconv_kernel<<<dim3(1024 / 32, 512 / 32),  blk>>>(W0, 512,  1024, w + W0_OFF);
    wconv_kernel<<<dim3(1024 / 32, 1024 / 32), blk>>>(W1, 1024, 1024, w + W1_OFF);
    wconv_kernel<<<dim3(1024 / 32, 1024 / 32), blk>>>(W2, 1024, 1024, w + W2_OFF);

    // 6-8. three GEMM layers (launch #6 = gemm L0 gets profiled)
    dim3 grid(D_ROUTE / 128, N_ROUTES / 256);   // (8, 64)
    gemm_fp16<<<grid, 256, smem_bytes>>>(512,  8,  actA, w + W0_OFF, b0, nullptr, actB);
    gemm_fp16<<<grid, 256, smem_bytes>>>(1024, 16, actB, w + W1_OFF, b1, nullptr, actA);
    gemm_fp16<<<grid, 256, smem_bytes>>>(1024, 16, actA, w + W2_OFF, b2, out, nullptr);
}

// round 10
// speedup vs baseline: 7.3979x; 1.1149x over previous
#include <cuda_runtime.h>
#include <cuda_fp16.h>
#include <cstdint>

// Problem constants
#define N_ROUTES  16384
#define ROUTE_LEN 32
#define D_GRAPH   512
#define D_ROUTE   1024
#define N_NODES   100000

// ---------------------------------------------------------------------------
// Device scratch (allocation-free).
// ---------------------------------------------------------------------------
__device__ __align__(256) __half g_ge16[(size_t)N_NODES * D_GRAPH];   // fp16 table
__device__ __align__(256) __half g_actA[(size_t)N_ROUTES * D_ROUTE];
__device__ __align__(256) __half g_actB[(size_t)N_ROUTES * D_ROUTE];
#define W0_OFF 0
#define W1_OFF (1024*512)
#define W2_OFF (1024*512 + 1024*1024)
#define W_ELEMS (1024*512 + 1024*1024 + 1024*1024)
__device__ __align__(256) __half g_w[W_ELEMS];

// ---------------------------------------------------------------------------
// Helpers
// ---------------------------------------------------------------------------
__device__ __forceinline__ uint32_t swz128(uint32_t b) { return b ^ ((b >> 3) & 0x70); }

__device__ __forceinline__ uint32_t smem_u32(const void* p) {
    uint32_t a;
    asm("{ .reg .u64 t; cvta.to.shared.u64 t, %1; cvt.u32.u64 %0, t; }" : "=r"(a) : "l"(p));
    return a;
}

__device__ __forceinline__ void cp16(uint32_t dst, const void* src) {
    asm volatile("cp.async.cg.shared.global [%0], [%1], 16;" :: "r"(dst), "l"(src) : "memory");
}
__device__ __forceinline__ void cp_commit() { asm volatile("cp.async.commit_group;" ::: "memory"); }
__device__ __forceinline__ void cp_wait1() { asm volatile("cp.async.wait_group 1;" ::: "memory"); }

__device__ __forceinline__ void ldsm_x4(uint32_t* r, uint32_t addr) {
    asm volatile("ldmatrix.sync.aligned.m8n8.x4.shared.b16 {%0,%1,%2,%3}, [%4];"
                 : "=r"(r[0]), "=r"(r[1]), "=r"(r[2]), "=r"(r[3]) : "r"(addr));
}

__device__ __forceinline__ void mma16816(float* d, const uint32_t* a, const uint32_t* b) {
    asm volatile(
        "mma.sync.aligned.m16n8k16.row.col.f32.f16.f16.f32 "
        "{%0,%1,%2,%3}, {%4,%5,%6,%7}, {%8,%9}, {%0,%1,%2,%3};"
        : "+f"(d[0]), "+f"(d[1]), "+f"(d[2]), "+f"(d[3])
        : "r"(a[0]), "r"(a[1]), "r"(a[2]), "r"(a[3]), "r"(b[0]), "r"(b[1]));
}

__device__ __forceinline__ uint4 hmax2x4(uint4 a, uint4 b) {
    __half2* pa = (__half2*)&a;
    __half2* pb = (__half2*)&b;
    uint4 r;
    __half2* pr = (__half2*)&r;
    pr[0] = __hmax2(pa[0], pb[0]);
    pr[1] = __hmax2(pa[1], pb[1]);
    pr[2] = __hmax2(pa[2], pb[2]);
    pr[3] = __hmax2(pa[3], pb[3]);
    return r;
}

// ---------------------------------------------------------------------------
// Table conversion: graph_embedding fp32 -> fp16 (leaves fp16 table hot in L2).
// ---------------------------------------------------------------------------
__global__ __launch_bounds__(256) void conv_kernel(
    const float* __restrict__ ge, __half* __restrict__ o)
{
    const size_t i = (size_t)blockIdx.x * 256 + threadIdx.x;   // 8 floats each
    const float4* p = (const float4*)ge;
    float4 a = p[2 * i];
    float4 b = p[2 * i + 1];
    __half2 h0 = __floats2half2_rn(a.x, a.y);
    __half2 h1 = __floats2half2_rn(a.z, a.w);
    __half2 h2 = __floats2half2_rn(b.x, b.y);
    __half2 h3 = __floats2half2_rn(b.z, b.w);
    uint4 u;
    u.x = *(uint32_t*)&h0; u.y = *(uint32_t*)&h1;
    u.z = *(uint32_t*)&h2; u.w = *(uint32_t*)&h3;
    ((uint4*)o)[i] = u;
}

// ---------------------------------------------------------------------------
// Gather + max on the fp16 table, per-route index-dtype self-detection.
// ---------------------------------------------------------------------------
__global__ __launch_bounds__(256) void gather_max_kernel(
    const __half* __restrict__ ge16,
    const unsigned int* __restrict__ w,
    __half* __restrict__ out)
{
    const int r = blockIdx.x;
    __shared__ int s_idx[ROUTE_LEN];
    __shared__ uint4 s_red[3][64];

    const int tid = threadIdx.x;
    if (tid < 32) {
        unsigned int odd = w[(size_t)r * 32 + 2 * (tid & 15) + 1];
        int is_i32 = __any_sync(0xFFFFFFFFu, (tid < 16) && odd != 0u);
        int v;
        if (is_i32) v = (int)w[(size_t)r * 32 + tid];
        else        v = (int)w[(size_t)r * 64 + 2 * tid];
        s_idx[tid] = v;
    }
    __syncthreads();

    const int g = tid & 63;
    const int q = tid >> 6;

    const uint4* row0 = (const uint4*)(ge16 + (size_t)s_idx[q * 8] * D_GRAPH);
    uint4 acc = __ldg(row0 + g);
    #pragma unroll 7
    for (int l = 1; l < 8; l++) {
        const uint4* row = (const uint4*)(ge16 + (size_t)s_idx[q * 8 + l] * D_GRAPH);
        acc = hmax2x4(acc, __ldg(row + g));
    }

    if (q) s_red[q - 1][g] = acc;
    __syncthreads();
    if (!q) {
        acc = hmax2x4(acc, s_red[0][g]);
        acc = hmax2x4(acc, s_red[1][g]);
        acc = hmax2x4(acc, s_red[2][g]);
        *(uint4*)(out + (size_t)r * D_GRAPH + g * 8) = acc;
    }
}

// ---------------------------------------------------------------------------
// Weight prep: W[K,N] fp32 -> transposed fp16 [N,K]
// ---------------------------------------------------------------------------
__global__ __launch_bounds__(256) void wconv_kernel(
    const float* __restrict__ W, int K, int N, __half* __restrict__ Wh)
{
    __shared__ float t[32][33];
    const int n0 = blockIdx.x * 32;
    const int k0 = blockIdx.y * 32;
    const int tx = threadIdx.x, ty = threadIdx.y;

    #pragma unroll
    for (int i = 0; i < 4; i++)
        t[ty + i * 8][tx] = W[(size_t)(k0 + ty + i * 8) * N + n0 + tx];
    __syncthreads();

    #pragma unroll
    for (int i = 0; i < 4; i++) {
        const int n = n0 + ty + i * 8;
        const int k = k0 + tx;
        Wh[(size_t)n * K + k] = __float2half_rn(t[tx][ty + i * 8]);
    }
}

// ---------------------------------------------------------------------------
// fp16 GEMM on mma.sync: C = relu(A @ B^T + bias)
// 128x128 CTA tile, 8 warps (2 M x 4 N), warp tile 64x32, m16n8k16.
// 3-stage buffer, 2-deep cp.async pipeline (32 KB/stage = 96 KB -> 2 CTAs/SM),
// single __syncthreads per chunk. SAFE stage rotation: tail load targets
// stage (c+2)%3 == (c-1)%3, which the top-of-iter barrier proved drained.
// ---------------------------------------------------------------------------
#define STAGE_BYTES 32768
#define T_A 0
#define T_B 16384

__device__ __forceinline__ void load_chunk(
    uint32_t sbase, int c, int tid, int m0, int n0, int K,
    const __half* A, const __half* B)
{
    const int r0  = tid >> 3;      // 0..31
    const int seg = tid & 7;
    const uint32_t st = sbase + (uint32_t)(c % 3) * STAGE_BYTES;
    const size_t koff = (size_t)c * 64 + seg * 8;
    #pragma unroll
    for (int i = 0; i < 4; i++) {
        const int row = r0 + i * 32;
        const uint32_t sw = swz128((uint32_t)(row * 128 + seg * 16));
        cp16(st + T_A + sw, A + (size_t)(m0 + row) * K + koff);
        cp16(st + T_B + sw, B + (size_t)(n0 + row) * K + koff);
    }
    cp_commit();
}

__global__ __launch_bounds__(256, 2) void gemm_fp16(
    int K, int nchunks,
    const __half* __restrict__ A, const __half* __restrict__ B,
    const float* __restrict__ bias,
    float* __restrict__ Cf, __half* __restrict__ Ch)
{
    extern __shared__ __align__(1024) char smem[];
    __shared__ float s_bias[128];

    const int tid  = threadIdx.x;
    const int wid  = tid >> 5;
    const int lane = tid & 31;
    const int m0 = blockIdx.y * 128;
    const int n0 = blockIdx.x * 128;
    const int wm = (wid >> 2) * 64;   // 0/64
    const int wn = (wid & 3) * 32;    // 0/32/64/96

    const uint32_t sbase = smem_u32(smem);
    if (tid < 128) s_bias[tid] = bias[n0 + tid];

    // Preload 2 chunks (2-deep pipeline over a 3-stage buffer)
    load_chunk(sbase, 0, tid, m0, n0, K, A, B);
    load_chunk(sbase, 1, tid, m0, n0, K, A, B);

    float acc[4][4][4];
    #pragma unroll
    for (int i = 0; i < 4; i++)
        #pragma unroll
        for (int j = 0; j < 4; j++)
            #pragma unroll
            for (int q = 0; q < 4; q++) acc[i][j][q] = 0.0f;

    for (int c = 0; c < nchunks; c++) {
        cp_wait1();        // chunk c's loads complete (≤1 group pending)
        __syncthreads();   // all warps done with chunk c-1 -> stage (c-1)%3 free

        const uint32_t st = sbase + (uint32_t)(c % 3) * STAGE_BYTES;

        #pragma unroll
        for (int ks = 0; ks < 4; ks++) {
            const uint32_t kb = ks * 32;

            // B fragments: 2 x ldsm_x4, each covering two adjacent n-tiles
            uint32_t bf[4][2];
            #pragma unroll
            for (int ntp = 0; ntp < 2; ntp++) {
                const uint32_t off = swz128(
                    (uint32_t)((wn + ntp * 16 + ((lane >> 4) & 1) * 8 + (lane & 7)) * 128)
                    + kb + ((lane >> 3) & 1) * 16);
                uint32_t r[4];
                ldsm_x4(r, st + T_B + off);
                bf[ntp * 2 + 0][0] = r[0]; bf[ntp * 2 + 0][1] = r[1];
                bf[ntp * 2 + 1][0] = r[2]; bf[ntp * 2 + 1][1] = r[3];
            }

            #pragma unroll
            for (int mt = 0; mt < 4; mt++) {
                const uint32_t aoff = swz128(
                    (uint32_t)((wm + mt * 16 + (lane & 15)) * 128) + kb + ((lane >> 4) & 1) * 16);
                uint32_t af[4];
                ldsm_x4(af, st + T_A + aoff);
                #pragma unroll
                for (int nt = 0; nt < 4; nt++)
                    mma16816(acc[mt][nt], af, bf[nt]);
            }
        }

        // Tail load into stage (c+2)%3 == (c-1)%3 (drained per top barrier)
        if (c + 2 < nchunks)
            load_chunk(sbase, c + 2, tid, m0, n0, K, A, B);
    }

    // Epilogue
    const int rbase = m0 + wm + (lane >> 2);
    const int cloc0 = wn + (lane & 3) * 2;
    #pragma unroll
    for (int mt = 0; mt < 4; mt++) {
        #pragma unroll
        for (int half = 0; half < 2; half++) {
            const int row = rbase + mt * 16 + half * 8;
            #pragma unroll
            for (int nt = 0; nt < 4; nt++) {
                const int cl = cloc0 + nt * 8;
                float v0 = fmaxf(acc[mt][nt][half * 2 + 0] + s_bias[cl + 0], 0.0f);
                float v1 = fmaxf(acc[mt][nt][half * 2 + 1] + s_bias[cl + 1], 0.0f);
                const size_t off = (size_t)row * D_ROUTE + n0 + cl;
                if (Cf) {
                    *(float2*)(Cf + off) = make_float2(v0, v1);
                } else {
                    __half2 hp = __halves2half2(__float2half_rn(v0), __float2half_rn(v1));
                    *(uint32_t*)(Ch + off) = *(uint32_t*)&hp;
                }
            }
        }
    }
}

// ---------------------------------------------------------------------------
// kernel_launch
// Inputs: graph_embedding, locations_idx, W0, b0, W1, b1, W2, b2
// ---------------------------------------------------------------------------
extern "C" void kernel_launch(void* const* d_in, const int* in_sizes, int n_in,
                              void* d_out, int out_size)
{
    const float* ge  = (const float*)d_in[0];
    const void*  idx = d_in[1];
    const float* W0  = (const float*)d_in[2];
    const float* b0  = (const float*)d_in[3];
    const float* W1  = (const float*)d_in[4];
    const float* b1  = (const float*)d_in[5];
    const float* W2  = (const float*)d_in[6];
    const float* b2  = (const float*)d_in[7];
    float* out = (float*)d_out;

    __half *ge16, *actA, *actB, *w;
    cudaGetSymbolAddress((void**)&ge16, g_ge16);
    cudaGetSymbolAddress((void**)&actA, g_actA);
    cudaGetSymbolAddress((void**)&actB, g_actB);
    cudaGetSymbolAddress((void**)&w,    g_w);

    const int smem_bytes = 3 * STAGE_BYTES;   // 96 KB -> 2 CTAs/SM
    cudaFuncSetAttribute(gemm_fp16, cudaFuncAttributeMaxDynamicSharedMemorySize, smem_bytes);

    // 1. fp32 -> fp16 table
    conv_kernel<<<25000, 256>>>(ge, ge16);

    // 2. gather + max (self-detecting index dtype) -> fp16 activations
    gather_max_kernel<<<N_ROUTES, 256>>>(ge16, (const unsigned int*)idx, actA);

    // 3-5. weight prep
    dim3 blk(32, 8);
    wconv_kernel<<<dim3(1024 / 32, 512 / 32),  blk>>>(W0, 512,  1024, w + W0_OFF);
    wconv_kernel<<<dim3(1024 / 32, 1024 / 32), blk>>>(W1, 1024, 1024, w + W1_OFF);
    wconv_kernel<<<dim3(1024 / 32, 1024 / 32), blk>>>(W2, 1024, 1024, w + W2_OFF);

    // 6-8. three GEMM layers
    dim3 grid(D_ROUTE / 128, N_ROUTES / 128);   // (8, 128) = 1024 CTAs
    gemm_fp16<<<grid, 256, smem_bytes>>>(512,  8,  actA, w + W0_OFF, b0, nullptr, actB);
    gemm_fp16<<<grid, 256, smem_bytes>>>(1024, 16, actB, w + W1_OFF, b1, nullptr, actA);
    gemm_fp16<<<grid, 256, smem_bytes>>>(1024, 16, actA, w + W2_OFF, b2, out, nullptr);
}